// round 1
// baseline (speedup 1.0000x reference)
#include <cuda_runtime.h>
#include <cstdint>

// ---------------- shared-memory weight layout (floats) ----------------
constexpr int O_L0H  = 0;      // 256  (16x16)
constexpr int O_L1H  = 256;    // 64   (8x8)
constexpr int O_L2H  = 320;    // 64
constexpr int O_L0A  = 384;    // 256
constexpr int O_L1A  = 640;    // 64
constexpr int O_L2A  = 704;    // 64
constexpr int O_W000 = 768;    // 4096 (16,16,16)
constexpr int O_W110 = 4864;   // 1024 (8,8,16)
constexpr int O_W220 = 5888;   // 1024
constexpr int O_W011 = 6912;   // 1024 (16,8,8)
constexpr int O_W101 = 7936;   // 1024 (8,16,8)
constexpr int O_W121 = 8960;   // 512  (8,8,8)
constexpr int O_W211 = 9472;   // 512
constexpr int O_W022 = 9984;   // 1024 (16,8,8)
constexpr int O_W202 = 11008;  // 1024 (8,16,8)
constexpr int O_W112 = 12032;  // 512
constexpr int O_W222 = 12544;  // 512
constexpr int SMEM_FLOATS = 13056;   // 52224 bytes

__device__ __forceinline__ float sigm(float v) {
    return 1.0f / (1.0f + __expf(-v));
}

__global__ void __launch_bounds__(256, 1)
e3nn_fctp_kernel(const float* __restrict__ x,
                 const float* __restrict__ l0h, const float* __restrict__ l1h, const float* __restrict__ l2h,
                 const float* __restrict__ l0a, const float* __restrict__ l1a, const float* __restrict__ l2a,
                 const float* __restrict__ w000, const float* __restrict__ w110, const float* __restrict__ w220,
                 const float* __restrict__ w011, const float* __restrict__ w101, const float* __restrict__ w121,
                 const float* __restrict__ w211, const float* __restrict__ w022, const float* __restrict__ w202,
                 const float* __restrict__ w112, const float* __restrict__ w222,
                 float* __restrict__ out, int rows)
{
    extern __shared__ float sm[];
    const int tid = threadIdx.x;

    // path normalizations (folded into the smem weight copies)
    const float s0   = 0.051031036307982884f;   // sqrt(1/384)
    const float s1   = 0.088388347648318447f;   // sqrt(3/384)
    const float i3   = 0.57735026918962576f;    // 1/sqrt(3)
    const float i6   = 0.40824829046386302f;    // 1/sqrt(6)
    const float c110 = s0 * i3;
    const float c1_3 = s1 * i3;
    const float c1_6 = s1 * i6;
    const float lin16 = 0.25f;                  // 1/sqrt(16)
    const float lin8  = 0.35355339059327379f;   // 1/sqrt(8)

    // ---- preprocess weights into shared memory (scaled) ----
    sm[O_L0H + tid] = l0h[tid] * lin16;
    sm[O_L0A + tid] = l0a[tid] * lin16;
    if (tid < 64) {
        sm[O_L1H + tid] = l1h[tid] * lin8;
        sm[O_L2H + tid] = l2h[tid] * lin8;
        sm[O_L1A + tid] = l1a[tid] * lin8;
        sm[O_L2A + tid] = l2a[tid] * lin8;
    }
    #pragma unroll
    for (int q = 0; q < 16; q++) {
        int i = q * 256 + tid;
        sm[O_W000 + i] = w000[i] * s0;
    }
    #pragma unroll
    for (int q = 0; q < 4; q++) {
        int i = q * 256 + tid;
        sm[O_W110 + i] = w110[i] * c110;
        sm[O_W220 + i] = w220[i] * c110;
        sm[O_W011 + i] = w011[i] * c1_3;
        sm[O_W101 + i] = w101[i] * c1_3;
        sm[O_W022 + i] = w022[i] * c1_3;
        sm[O_W202 + i] = w202[i] * c1_3;
    }
    #pragma unroll
    for (int q = 0; q < 2; q++) {
        int i = q * 256 + tid;
        sm[O_W121 + i] = w121[i] * c1_6;
        sm[O_W211 + i] = w211[i] * c1_6;
        sm[O_W112 + i] = w112[i] * c1_6;
        sm[O_W222 + i] = w222[i] * c1_6;
    }
    __syncthreads();

    const int stride = gridDim.x * 256;
    #pragma unroll 1
    for (int row = blockIdx.x * 256 + tid; row < rows; row += stride) {
        const float* xr = x + (size_t)row * 64u;

        // ---- load input row ----
        float xv[64];
        #pragma unroll
        for (int q = 0; q < 16; q++) {
            float4 t = __ldg(((const float4*)xr) + q);
            xv[4*q+0] = t.x; xv[4*q+1] = t.y; xv[4*q+2] = t.z; xv[4*q+3] = t.w;
        }

        // ---- equivariant linears: h (plain), a (pre-activation) ----
        float h0[16], a0[16];
        #pragma unroll
        for (int v = 0; v < 16; v++) { h0[v] = 0.f; a0[v] = 0.f; }
        #pragma unroll
        for (int u = 0; u < 16; u++) {
            const float xu = xv[u];
            #pragma unroll
            for (int v = 0; v < 16; v++) {
                h0[v] += xu * sm[O_L0H + u*16 + v];
                a0[v] += xu * sm[O_L0A + u*16 + v];
            }
        }
        float h1[24], a1[24], h2[24], a2[24];
        #pragma unroll
        for (int j = 0; j < 24; j++) { h1[j]=0.f; a1[j]=0.f; h2[j]=0.f; a2[j]=0.f; }
        #pragma unroll
        for (int u = 0; u < 8; u++) {
            const float x10 = xv[16+u*3+0], x11 = xv[16+u*3+1], x12 = xv[16+u*3+2];
            const float x20 = xv[40+u*3+0], x21 = xv[40+u*3+1], x22 = xv[40+u*3+2];
            #pragma unroll
            for (int v = 0; v < 8; v++) {
                const float wh1 = sm[O_L1H + u*8 + v];
                const float wa1 = sm[O_L1A + u*8 + v];
                const float wh2 = sm[O_L2H + u*8 + v];
                const float wa2 = sm[O_L2A + u*8 + v];
                h1[v*3+0] += x10*wh1; h1[v*3+1] += x11*wh1; h1[v*3+2] += x12*wh1;
                a1[v*3+0] += x10*wa1; a1[v*3+1] += x11*wa1; a1[v*3+2] += x12*wa1;
                h2[v*3+0] += x20*wh2; h2[v*3+1] += x21*wh2; h2[v*3+2] += x22*wh2;
                a2[v*3+0] += x20*wa2; a2[v*3+1] += x21*wa2; a2[v*3+2] += x22*wa2;
            }
        }

        // ---- NormActivation on a-branch ----
        #pragma unroll
        for (int u = 0; u < 16; u++) {
            const float v = a0[u];
            const float nn = fabsf(v);
            const float s = sigm(nn);
            a0[u] = (nn == 0.f) ? 0.f : v * s / nn;
        }
        #pragma unroll
        for (int u = 0; u < 8; u++) {
            {
                const float b0=a1[u*3], b1=a1[u*3+1], b2=a1[u*3+2];
                const float nrm = sqrtf(b0*b0 + b1*b1 + b2*b2);
                const float f = sigm(nrm) / ((nrm == 0.f) ? 1.f : nrm);
                a1[u*3] = b0*f; a1[u*3+1] = b1*f; a1[u*3+2] = b2*f;
            }
            {
                const float b0=a2[u*3], b1=a2[u*3+1], b2=a2[u*3+2];
                const float nrm = sqrtf(b0*b0 + b1*b1 + b2*b2);
                const float f = sigm(nrm) / ((nrm == 0.f) ? 1.f : nrm);
                a2[u*3] = b0*f; a2[u*3+1] = b1*f; a2[u*3+2] = b2*f;
            }
        }

        float* orow = out + (size_t)row * 64u;

        // ================= out0 (scalars, 16) =================
        {
            float o0[16];
            #pragma unroll
            for (int w = 0; w < 16; w++) o0[w] = 0.f;

            // path (0,0,0)
            #pragma unroll
            for (int u = 0; u < 16; u++) {
                const float hu = h0[u];
                #pragma unroll
                for (int v = 0; v < 16; v++) {
                    const float p = hu * a0[v];
                    const float4* wp = (const float4*)(sm + O_W000 + (u*16 + v)*16);
                    #pragma unroll
                    for (int q = 0; q < 4; q++) {
                        const float4 wv = wp[q];
                        o0[4*q+0] += p*wv.x; o0[4*q+1] += p*wv.y;
                        o0[4*q+2] += p*wv.z; o0[4*q+3] += p*wv.w;
                    }
                }
            }
            // path (1,1,0): dot(h1[u], a1[v])
            #pragma unroll
            for (int u = 0; u < 8; u++) {
                const float hxx=h1[u*3], hyy=h1[u*3+1], hzz=h1[u*3+2];
                #pragma unroll
                for (int v = 0; v < 8; v++) {
                    const float d = hxx*a1[v*3] + hyy*a1[v*3+1] + hzz*a1[v*3+2];
                    const float4* wp = (const float4*)(sm + O_W110 + (u*8 + v)*16);
                    #pragma unroll
                    for (int q = 0; q < 4; q++) {
                        const float4 wv = wp[q];
                        o0[4*q+0] += d*wv.x; o0[4*q+1] += d*wv.y;
                        o0[4*q+2] += d*wv.z; o0[4*q+3] += d*wv.w;
                    }
                }
            }
            // path (2,2,0)
            #pragma unroll
            for (int u = 0; u < 8; u++) {
                const float hxx=h2[u*3], hyy=h2[u*3+1], hzz=h2[u*3+2];
                #pragma unroll
                for (int v = 0; v < 8; v++) {
                    const float d = hxx*a2[v*3] + hyy*a2[v*3+1] + hzz*a2[v*3+2];
                    const float4* wp = (const float4*)(sm + O_W220 + (u*8 + v)*16);
                    #pragma unroll
                    for (int q = 0; q < 4; q++) {
                        const float4 wv = wp[q];
                        o0[4*q+0] += d*wv.x; o0[4*q+1] += d*wv.y;
                        o0[4*q+2] += d*wv.z; o0[4*q+3] += d*wv.w;
                    }
                }
            }
            float4* o4 = (float4*)orow;
            #pragma unroll
            for (int q = 0; q < 4; q++)
                o4[q] = make_float4(o0[4*q], o0[4*q+1], o0[4*q+2], o0[4*q+3]);
        }

        // ================= out1 (8x1o -> 24) =================
        {
            float o1[24];
            #pragma unroll
            for (int j = 0; j < 24; j++) o1[j] = 0.f;

            float M[64];
            // path (0,1,1): M[v,w] = sum_u h0[u] * W011[u,v,w]
            #pragma unroll
            for (int j = 0; j < 64; j++) M[j] = 0.f;
            #pragma unroll
            for (int u = 0; u < 16; u++) {
                const float hu = h0[u];
                const float4* wp = (const float4*)(sm + O_W011 + u*64);
                #pragma unroll
                for (int q = 0; q < 16; q++) {
                    const float4 wv = wp[q];
                    M[4*q+0] += hu*wv.x; M[4*q+1] += hu*wv.y;
                    M[4*q+2] += hu*wv.z; M[4*q+3] += hu*wv.w;
                }
            }
            #pragma unroll
            for (int v = 0; v < 8; v++) {
                const float b0=a1[v*3], b1=a1[v*3+1], b2=a1[v*3+2];
                #pragma unroll
                for (int w = 0; w < 8; w++) {
                    const float m = M[v*8 + w];
                    o1[w*3+0] += b0*m; o1[w*3+1] += b1*m; o1[w*3+2] += b2*m;
                }
            }
            // path (1,0,1): M[u,w] = sum_v a0[v] * W101[u,v,w]
            #pragma unroll
            for (int j = 0; j < 64; j++) M[j] = 0.f;
            #pragma unroll
            for (int v = 0; v < 16; v++) {
                const float av = a0[v];
                #pragma unroll
                for (int u = 0; u < 8; u++) {
                    const float4* wp = (const float4*)(sm + O_W101 + u*128 + v*8);
                    const float4 wva = wp[0], wvb = wp[1];
                    M[u*8+0] += av*wva.x; M[u*8+1] += av*wva.y;
                    M[u*8+2] += av*wva.z; M[u*8+3] += av*wva.w;
                    M[u*8+4] += av*wvb.x; M[u*8+5] += av*wvb.y;
                    M[u*8+6] += av*wvb.z; M[u*8+7] += av*wvb.w;
                }
            }
            #pragma unroll
            for (int u = 0; u < 8; u++) {
                const float b0=h1[u*3], b1=h1[u*3+1], b2=h1[u*3+2];
                #pragma unroll
                for (int w = 0; w < 8; w++) {
                    const float m = M[u*8 + w];
                    o1[w*3+0] += b0*m; o1[w*3+1] += b1*m; o1[w*3+2] += b2*m;
                }
            }
            // path (1,2,1): cross(h1[u], a2[v])
            #pragma unroll
            for (int u = 0; u < 8; u++) {
                const float ax=h1[u*3], ay=h1[u*3+1], az=h1[u*3+2];
                #pragma unroll
                for (int v = 0; v < 8; v++) {
                    const float bx=a2[v*3], by=a2[v*3+1], bz=a2[v*3+2];
                    const float cx = ay*bz - az*by;
                    const float cy = az*bx - ax*bz;
                    const float cz = ax*by - ay*bx;
                    const float4* wp = (const float4*)(sm + O_W121 + (u*8+v)*8);
                    const float4 wva = wp[0], wvb = wp[1];
                    float wt[8] = {wva.x,wva.y,wva.z,wva.w,wvb.x,wvb.y,wvb.z,wvb.w};
                    #pragma unroll
                    for (int w = 0; w < 8; w++) {
                        const float m = wt[w];
                        o1[w*3+0] += cx*m; o1[w*3+1] += cy*m; o1[w*3+2] += cz*m;
                    }
                }
            }
            // path (2,1,1): cross(h2[u], a1[v])
            #pragma unroll
            for (int u = 0; u < 8; u++) {
                const float ax=h2[u*3], ay=h2[u*3+1], az=h2[u*3+2];
                #pragma unroll
                for (int v = 0; v < 8; v++) {
                    const float bx=a1[v*3], by=a1[v*3+1], bz=a1[v*3+2];
                    const float cx = ay*bz - az*by;
                    const float cy = az*bx - ax*bz;
                    const float cz = ax*by - ay*bx;
                    const float4* wp = (const float4*)(sm + O_W211 + (u*8+v)*8);
                    const float4 wva = wp[0], wvb = wp[1];
                    float wt[8] = {wva.x,wva.y,wva.z,wva.w,wvb.x,wvb.y,wvb.z,wvb.w};
                    #pragma unroll
                    for (int w = 0; w < 8; w++) {
                        const float m = wt[w];
                        o1[w*3+0] += cx*m; o1[w*3+1] += cy*m; o1[w*3+2] += cz*m;
                    }
                }
            }
            float4* o4 = (float4*)(orow + 16);
            #pragma unroll
            for (int q = 0; q < 6; q++)
                o4[q] = make_float4(o1[4*q], o1[4*q+1], o1[4*q+2], o1[4*q+3]);
        }

        // ================= out2 (8x1e -> 24) =================
        {
            float o2[24];
            #pragma unroll
            for (int j = 0; j < 24; j++) o2[j] = 0.f;

            float M[64];
            // path (0,2,2): M[v,w] = sum_u h0[u] * W022[u,v,w]
            #pragma unroll
            for (int j = 0; j < 64; j++) M[j] = 0.f;
            #pragma unroll
            for (int u = 0; u < 16; u++) {
                const float hu = h0[u];
                const float4* wp = (const float4*)(sm + O_W022 + u*64);
                #pragma unroll
                for (int q = 0; q < 16; q++) {
                    const float4 wv = wp[q];
                    M[4*q+0] += hu*wv.x; M[4*q+1] += hu*wv.y;
                    M[4*q+2] += hu*wv.z; M[4*q+3] += hu*wv.w;
                }
            }
            #pragma unroll
            for (int v = 0; v < 8; v++) {
                const float b0=a2[v*3], b1=a2[v*3+1], b2=a2[v*3+2];
                #pragma unroll
                for (int w = 0; w < 8; w++) {
                    const float m = M[v*8 + w];
                    o2[w*3+0] += b0*m; o2[w*3+1] += b1*m; o2[w*3+2] += b2*m;
                }
            }
            // path (2,0,2): M[u,w] = sum_v a0[v] * W202[u,v,w]
            #pragma unroll
            for (int j = 0; j < 64; j++) M[j] = 0.f;
            #pragma unroll
            for (int v = 0; v < 16; v++) {
                const float av = a0[v];
                #pragma unroll
                for (int u = 0; u < 8; u++) {
                    const float4* wp = (const float4*)(sm + O_W202 + u*128 + v*8);
                    const float4 wva = wp[0], wvb = wp[1];
                    M[u*8+0] += av*wva.x; M[u*8+1] += av*wva.y;
                    M[u*8+2] += av*wva.z; M[u*8+3] += av*wva.w;
                    M[u*8+4] += av*wvb.x; M[u*8+5] += av*wvb.y;
                    M[u*8+6] += av*wvb.z; M[u*8+7] += av*wvb.w;
                }
            }
            #pragma unroll
            for (int u = 0; u < 8; u++) {
                const float b0=h2[u*3], b1=h2[u*3+1], b2=h2[u*3+2];
                #pragma unroll
                for (int w = 0; w < 8; w++) {
                    const float m = M[u*8 + w];
                    o2[w*3+0] += b0*m; o2[w*3+1] += b1*m; o2[w*3+2] += b2*m;
                }
            }
            // path (1,1,2): cross(h1[u], a1[v])
            #pragma unroll
            for (int u = 0; u < 8; u++) {
                const float ax=h1[u*3], ay=h1[u*3+1], az=h1[u*3+2];
                #pragma unroll
                for (int v = 0; v < 8; v++) {
                    const float bx=a1[v*3], by=a1[v*3+1], bz=a1[v*3+2];
                    const float cx = ay*bz - az*by;
                    const float cy = az*bx - ax*bz;
                    const float cz = ax*by - ay*bx;
                    const float4* wp = (const float4*)(sm + O_W112 + (u*8+v)*8);
                    const float4 wva = wp[0], wvb = wp[1];
                    float wt[8] = {wva.x,wva.y,wva.z,wva.w,wvb.x,wvb.y,wvb.z,wvb.w};
                    #pragma unroll
                    for (int w = 0; w < 8; w++) {
                        const float m = wt[w];
                        o2[w*3+0] += cx*m; o2[w*3+1] += cy*m; o2[w*3+2] += cz*m;
                    }
                }
            }
            // path (2,2,2): cross(h2[u], a2[v])
            #pragma unroll
            for (int u = 0; u < 8; u++) {
                const float ax=h2[u*3], ay=h2[u*3+1], az=h2[u*3+2];
                #pragma unroll
                for (int v = 0; v < 8; v++) {
                    const float bx=a2[v*3], by=a2[v*3+1], bz=a2[v*3+2];
                    const float cx = ay*bz - az*by;
                    const float cy = az*bx - ax*bz;
                    const float cz = ax*by - ay*bx;
                    const float4* wp = (const float4*)(sm + O_W222 + (u*8+v)*8);
                    const float4 wva = wp[0], wvb = wp[1];
                    float wt[8] = {wva.x,wva.y,wva.z,wva.w,wvb.x,wvb.y,wvb.z,wvb.w};
                    #pragma unroll
                    for (int w = 0; w < 8; w++) {
                        const float m = wt[w];
                        o2[w*3+0] += cx*m; o2[w*3+1] += cy*m; o2[w*3+2] += cz*m;
                    }
                }
            }
            float4* o4 = (float4*)(orow + 40);
            #pragma unroll
            for (int q = 0; q < 6; q++)
                o4[q] = make_float4(o2[4*q], o2[4*q+1], o2[4*q+2], o2[4*q+3]);
        }
    }
}

extern "C" void kernel_launch(void* const* d_in, const int* in_sizes, int n_in,
                              void* d_out, int out_size)
{
    const float* x    = (const float*)d_in[0];
    const float* l0h  = (const float*)d_in[1];
    const float* l1h  = (const float*)d_in[2];
    const float* l2h  = (const float*)d_in[3];
    const float* l0a  = (const float*)d_in[4];
    const float* l1a  = (const float*)d_in[5];
    const float* l2a  = (const float*)d_in[6];
    const float* w000 = (const float*)d_in[7];
    const float* w110 = (const float*)d_in[8];
    const float* w220 = (const float*)d_in[9];
    const float* w011 = (const float*)d_in[10];
    const float* w101 = (const float*)d_in[11];
    const float* w121 = (const float*)d_in[12];
    const float* w211 = (const float*)d_in[13];
    const float* w022 = (const float*)d_in[14];
    const float* w202 = (const float*)d_in[15];
    const float* w112 = (const float*)d_in[16];
    const float* w222 = (const float*)d_in[17];
    float* out = (float*)d_out;

    const int rows = in_sizes[0] / 64;
    const size_t smem_bytes = SMEM_FLOATS * sizeof(float);
    cudaFuncSetAttribute(e3nn_fctp_kernel,
                         cudaFuncAttributeMaxDynamicSharedMemorySize,
                         (int)smem_bytes);

    const int block = 256;
    const int grid = 1024;   // grid-stride: ~2 rows per thread at N=524288
    e3nn_fctp_kernel<<<grid, block, smem_bytes>>>(
        x, l0h, l1h, l2h, l0a, l1a, l2a,
        w000, w110, w220, w011, w101, w121, w211, w022, w202, w112, w222,
        out, rows);
}

// round 2
// speedup vs baseline: 1.5120x; 1.5120x over previous
#include <cuda_runtime.h>
#include <cstdint>

// ---------------- shared-memory weight layout (floats) ----------------
constexpr int O_L0H  = 0;      // 256  (16x16)
constexpr int O_L1H  = 256;    // 64   (8x8)
constexpr int O_L2H  = 320;    // 64
constexpr int O_L0A  = 384;    // 256
constexpr int O_L1A  = 640;    // 64
constexpr int O_L2A  = 704;    // 64
constexpr int O_W000 = 768;    // 4096 (16,16,16)
constexpr int O_W110 = 4864;   // 1024 (8,8,16)
constexpr int O_W220 = 5888;   // 1024
constexpr int O_W011 = 6912;   // 1024 (16,8,8)
constexpr int O_W101 = 7936;   // 1024 (8,16,8)
constexpr int O_W121 = 8960;   // 512  (8,8,8)
constexpr int O_W211 = 9472;   // 512
constexpr int O_W022 = 9984;   // 1024 (16,8,8)
constexpr int O_W202 = 11008;  // 1024 (8,16,8)
constexpr int O_W112 = 12032;  // 512
constexpr int O_W222 = 12544;  // 512
constexpr int SMEM_FLOATS = 13056;   // 52224 bytes

using u64t = unsigned long long;

__device__ __forceinline__ u64t pk2(float lo, float hi) {
    u64t r; asm("mov.b64 %0,{%1,%2};" : "=l"(r) : "f"(lo), "f"(hi)); return r;
}
__device__ __forceinline__ u64t dup2(float v) { return pk2(v, v); }
__device__ __forceinline__ float2 up2(u64t p) {
    float2 t; asm("mov.b64 {%0,%1},%2;" : "=f"(t.x), "=f"(t.y) : "l"(p)); return t;
}
__device__ __forceinline__ u64t f2fma(u64t a, u64t b, u64t c) {
    u64t d; asm("fma.rn.f32x2 %0,%1,%2,%3;" : "=l"(d) : "l"(a), "l"(b), "l"(c)); return d;
}

__device__ __forceinline__ float sigm(float v) {
    return 1.0f / (1.0f + __expf(-v));
}

__global__ void __launch_bounds__(256, 1)
e3nn_fctp_kernel(const float* __restrict__ x,
                 const float* __restrict__ l0h, const float* __restrict__ l1h, const float* __restrict__ l2h,
                 const float* __restrict__ l0a, const float* __restrict__ l1a, const float* __restrict__ l2a,
                 const float* __restrict__ w000, const float* __restrict__ w110, const float* __restrict__ w220,
                 const float* __restrict__ w011, const float* __restrict__ w101, const float* __restrict__ w121,
                 const float* __restrict__ w211, const float* __restrict__ w022, const float* __restrict__ w202,
                 const float* __restrict__ w112, const float* __restrict__ w222,
                 float* __restrict__ out, int rows)
{
    extern __shared__ float sm[];
    const int tid = threadIdx.x;

    // path normalizations (folded into the smem weight copies)
    const float s0   = 0.051031036307982884f;   // sqrt(1/384)
    const float s1   = 0.088388347648318447f;   // sqrt(3/384)
    const float i3   = 0.57735026918962576f;    // 1/sqrt(3)
    const float i6   = 0.40824829046386302f;    // 1/sqrt(6)
    const float c110 = s0 * i3;
    const float c1_3 = s1 * i3;
    const float c1_6 = s1 * i6;
    const float lin16 = 0.25f;                  // 1/sqrt(16)
    const float lin8  = 0.35355339059327379f;   // 1/sqrt(8)

    // ---- preprocess weights into shared memory (scaled) ----
    sm[O_L0H + tid] = l0h[tid] * lin16;
    sm[O_L0A + tid] = l0a[tid] * lin16;
    if (tid < 64) {
        sm[O_L1H + tid] = l1h[tid] * lin8;
        sm[O_L2H + tid] = l2h[tid] * lin8;
        sm[O_L1A + tid] = l1a[tid] * lin8;
        sm[O_L2A + tid] = l2a[tid] * lin8;
    }
    #pragma unroll
    for (int q = 0; q < 16; q++) {
        int i = q * 256 + tid;
        sm[O_W000 + i] = w000[i] * s0;
    }
    #pragma unroll
    for (int q = 0; q < 4; q++) {
        int i = q * 256 + tid;
        sm[O_W110 + i] = w110[i] * c110;
        sm[O_W220 + i] = w220[i] * c110;
        sm[O_W011 + i] = w011[i] * c1_3;
        sm[O_W101 + i] = w101[i] * c1_3;
        sm[O_W022 + i] = w022[i] * c1_3;
        sm[O_W202 + i] = w202[i] * c1_3;
    }
    #pragma unroll
    for (int q = 0; q < 2; q++) {
        int i = q * 256 + tid;
        sm[O_W121 + i] = w121[i] * c1_6;
        sm[O_W211 + i] = w211[i] * c1_6;
        sm[O_W112 + i] = w112[i] * c1_6;
        sm[O_W222 + i] = w222[i] * c1_6;
    }
    __syncthreads();

    const int stride = gridDim.x * 256;
    #pragma unroll 1
    for (int row = blockIdx.x * 256 + tid; row < rows; row += stride) {
        const float* xr = x + (size_t)row * 64u;

        // ---- load input row ----
        float xv[64];
        #pragma unroll
        for (int q = 0; q < 16; q++) {
            float4 t = __ldg(((const float4*)xr) + q);
            xv[4*q+0] = t.x; xv[4*q+1] = t.y; xv[4*q+2] = t.z; xv[4*q+3] = t.w;
        }

        // ---- l=0 linear (packed over v pairs) ----
        u64t h0p[8], a0p[8];
        #pragma unroll
        for (int q = 0; q < 8; q++) { h0p[q] = 0ull; a0p[q] = 0ull; }
        #pragma unroll
        for (int u = 0; u < 16; u++) {
            const u64t xu2 = dup2(xv[u]);
            const ulonglong2* wh = (const ulonglong2*)(sm + O_L0H + u*16);
            const ulonglong2* wa = (const ulonglong2*)(sm + O_L0A + u*16);
            #pragma unroll
            for (int j = 0; j < 4; j++) {
                const ulonglong2 th = wh[j];
                h0p[2*j+0] = f2fma(xu2, th.x, h0p[2*j+0]);
                h0p[2*j+1] = f2fma(xu2, th.y, h0p[2*j+1]);
                const ulonglong2 ta = wa[j];
                a0p[2*j+0] = f2fma(xu2, ta.x, a0p[2*j+0]);
                a0p[2*j+1] = f2fma(xu2, ta.y, a0p[2*j+1]);
            }
        }
        float h0[16], a0[16];
        #pragma unroll
        for (int q = 0; q < 8; q++) {
            float2 th = up2(h0p[q]); h0[2*q] = th.x; h0[2*q+1] = th.y;
            float2 ta = up2(a0p[q]); a0[2*q] = ta.x; a0[2*q+1] = ta.y;
        }

        // ---- l=1 linears (scalar) ----
        float h1[24], a1[24], h2[24], a2[24];
        #pragma unroll
        for (int j = 0; j < 24; j++) { h1[j]=0.f; a1[j]=0.f; h2[j]=0.f; a2[j]=0.f; }
        #pragma unroll
        for (int u = 0; u < 8; u++) {
            const float x10 = xv[16+u*3+0], x11 = xv[16+u*3+1], x12 = xv[16+u*3+2];
            const float x20 = xv[40+u*3+0], x21 = xv[40+u*3+1], x22 = xv[40+u*3+2];
            #pragma unroll
            for (int v = 0; v < 8; v++) {
                const float wh1 = sm[O_L1H + u*8 + v];
                const float wa1 = sm[O_L1A + u*8 + v];
                const float wh2 = sm[O_L2H + u*8 + v];
                const float wa2 = sm[O_L2A + u*8 + v];
                h1[v*3+0] += x10*wh1; h1[v*3+1] += x11*wh1; h1[v*3+2] += x12*wh1;
                a1[v*3+0] += x10*wa1; a1[v*3+1] += x11*wa1; a1[v*3+2] += x12*wa1;
                h2[v*3+0] += x20*wh2; h2[v*3+1] += x21*wh2; h2[v*3+2] += x22*wh2;
                a2[v*3+0] += x20*wa2; a2[v*3+1] += x21*wa2; a2[v*3+2] += x22*wa2;
            }
        }

        // ---- NormActivation on a-branch ----
        #pragma unroll
        for (int u = 0; u < 16; u++) {
            const float v = a0[u];
            const float nn = fabsf(v);
            const float s = sigm(nn);
            a0[u] = (nn == 0.f) ? 0.f : v * s / nn;
        }
        #pragma unroll
        for (int u = 0; u < 8; u++) {
            {
                const float b0=a1[u*3], b1=a1[u*3+1], b2=a1[u*3+2];
                const float nrm = sqrtf(b0*b0 + b1*b1 + b2*b2);
                const float f = sigm(nrm) / ((nrm == 0.f) ? 1.f : nrm);
                a1[u*3] = b0*f; a1[u*3+1] = b1*f; a1[u*3+2] = b2*f;
            }
            {
                const float b0=a2[u*3], b1=a2[u*3+1], b2=a2[u*3+2];
                const float nrm = sqrtf(b0*b0 + b1*b1 + b2*b2);
                const float f = sigm(nrm) / ((nrm == 0.f) ? 1.f : nrm);
                a2[u*3] = b0*f; a2[u*3+1] = b1*f; a2[u*3+2] = b2*f;
            }
        }

        float* orow = out + (size_t)row * 64u;

        // ================= out0 (scalars, 16) — packed over w =================
        {
            u64t o0[8];
            #pragma unroll
            for (int q = 0; q < 8; q++) o0[q] = 0ull;

            // path (0,0,0)
            #pragma unroll
            for (int u = 0; u < 16; u++) {
                const float hu = h0[u];
                #pragma unroll
                for (int v = 0; v < 16; v++) {
                    const u64t p2 = dup2(hu * a0[v]);
                    const ulonglong2* wp = (const ulonglong2*)(sm + O_W000 + (u*16 + v)*16);
                    #pragma unroll
                    for (int j = 0; j < 4; j++) {
                        const ulonglong2 t = wp[j];
                        o0[2*j+0] = f2fma(p2, t.x, o0[2*j+0]);
                        o0[2*j+1] = f2fma(p2, t.y, o0[2*j+1]);
                    }
                }
            }
            // path (1,1,0)
            #pragma unroll
            for (int u = 0; u < 8; u++) {
                const float hxx=h1[u*3], hyy=h1[u*3+1], hzz=h1[u*3+2];
                #pragma unroll
                for (int v = 0; v < 8; v++) {
                    const float d = hxx*a1[v*3] + hyy*a1[v*3+1] + hzz*a1[v*3+2];
                    const u64t d2 = dup2(d);
                    const ulonglong2* wp = (const ulonglong2*)(sm + O_W110 + (u*8 + v)*16);
                    #pragma unroll
                    for (int j = 0; j < 4; j++) {
                        const ulonglong2 t = wp[j];
                        o0[2*j+0] = f2fma(d2, t.x, o0[2*j+0]);
                        o0[2*j+1] = f2fma(d2, t.y, o0[2*j+1]);
                    }
                }
            }
            // path (2,2,0)
            #pragma unroll
            for (int u = 0; u < 8; u++) {
                const float hxx=h2[u*3], hyy=h2[u*3+1], hzz=h2[u*3+2];
                #pragma unroll
                for (int v = 0; v < 8; v++) {
                    const float d = hxx*a2[v*3] + hyy*a2[v*3+1] + hzz*a2[v*3+2];
                    const u64t d2 = dup2(d);
                    const ulonglong2* wp = (const ulonglong2*)(sm + O_W220 + (u*8 + v)*16);
                    #pragma unroll
                    for (int j = 0; j < 4; j++) {
                        const ulonglong2 t = wp[j];
                        o0[2*j+0] = f2fma(d2, t.x, o0[2*j+0]);
                        o0[2*j+1] = f2fma(d2, t.y, o0[2*j+1]);
                    }
                }
            }
            ulonglong2* o4 = (ulonglong2*)orow;
            #pragma unroll
            for (int j = 0; j < 4; j++) {
                ulonglong2 t; t.x = o0[2*j]; t.y = o0[2*j+1];
                o4[j] = t;
            }
        }

        // ================= out1 (8x1o -> 24) =================
        {
            u64t o1[12];   // o1[w2*3+i] = comp i for outputs (2*w2, 2*w2+1)
            #pragma unroll
            for (int j = 0; j < 12; j++) o1[j] = 0ull;

            u64t M[32];    // M[v*4+w2] packed over w
            // path (0,1,1): M[v,w] = sum_u h0[u] * W011[u,v,w]
            #pragma unroll
            for (int j = 0; j < 32; j++) M[j] = 0ull;
            #pragma unroll
            for (int u = 0; u < 16; u++) {
                const u64t hu2 = dup2(h0[u]);
                const ulonglong2* wp = (const ulonglong2*)(sm + O_W011 + u*64);
                #pragma unroll
                for (int j = 0; j < 16; j++) {
                    const ulonglong2 t = wp[j];
                    M[2*j+0] = f2fma(hu2, t.x, M[2*j+0]);
                    M[2*j+1] = f2fma(hu2, t.y, M[2*j+1]);
                }
            }
            #pragma unroll
            for (int v = 0; v < 8; v++) {
                const u64t b0 = dup2(a1[v*3]), b1 = dup2(a1[v*3+1]), b2 = dup2(a1[v*3+2]);
                #pragma unroll
                for (int w2 = 0; w2 < 4; w2++) {
                    const u64t m = M[v*4 + w2];
                    o1[w2*3+0] = f2fma(b0, m, o1[w2*3+0]);
                    o1[w2*3+1] = f2fma(b1, m, o1[w2*3+1]);
                    o1[w2*3+2] = f2fma(b2, m, o1[w2*3+2]);
                }
            }
            // path (1,0,1): M[u,w] = sum_v a0[v] * W101[u,v,w]
            #pragma unroll
            for (int j = 0; j < 32; j++) M[j] = 0ull;
            #pragma unroll
            for (int v = 0; v < 16; v++) {
                const u64t av2 = dup2(a0[v]);
                #pragma unroll
                for (int u = 0; u < 8; u++) {
                    const ulonglong2* wp = (const ulonglong2*)(sm + O_W101 + u*128 + v*8);
                    const ulonglong2 ta = wp[0], tb = wp[1];
                    M[u*4+0] = f2fma(av2, ta.x, M[u*4+0]);
                    M[u*4+1] = f2fma(av2, ta.y, M[u*4+1]);
                    M[u*4+2] = f2fma(av2, tb.x, M[u*4+2]);
                    M[u*4+3] = f2fma(av2, tb.y, M[u*4+3]);
                }
            }
            #pragma unroll
            for (int u = 0; u < 8; u++) {
                const u64t b0 = dup2(h1[u*3]), b1 = dup2(h1[u*3+1]), b2 = dup2(h1[u*3+2]);
                #pragma unroll
                for (int w2 = 0; w2 < 4; w2++) {
                    const u64t m = M[u*4 + w2];
                    o1[w2*3+0] = f2fma(b0, m, o1[w2*3+0]);
                    o1[w2*3+1] = f2fma(b1, m, o1[w2*3+1]);
                    o1[w2*3+2] = f2fma(b2, m, o1[w2*3+2]);
                }
            }
            // path (1,2,1): cross(h1[u], a2[v])
            #pragma unroll
            for (int u = 0; u < 8; u++) {
                const float ax=h1[u*3], ay=h1[u*3+1], az=h1[u*3+2];
                #pragma unroll
                for (int v = 0; v < 8; v++) {
                    const float bx=a2[v*3], by=a2[v*3+1], bz=a2[v*3+2];
                    const u64t cx = dup2(ay*bz - az*by);
                    const u64t cy = dup2(az*bx - ax*bz);
                    const u64t cz = dup2(ax*by - ay*bx);
                    const ulonglong2* wp = (const ulonglong2*)(sm + O_W121 + (u*8+v)*8);
                    const ulonglong2 ta = wp[0], tb = wp[1];
                    const u64t wv[4] = {ta.x, ta.y, tb.x, tb.y};
                    #pragma unroll
                    for (int w2 = 0; w2 < 4; w2++) {
                        o1[w2*3+0] = f2fma(cx, wv[w2], o1[w2*3+0]);
                        o1[w2*3+1] = f2fma(cy, wv[w2], o1[w2*3+1]);
                        o1[w2*3+2] = f2fma(cz, wv[w2], o1[w2*3+2]);
                    }
                }
            }
            // path (2,1,1): cross(h2[u], a1[v])
            #pragma unroll
            for (int u = 0; u < 8; u++) {
                const float ax=h2[u*3], ay=h2[u*3+1], az=h2[u*3+2];
                #pragma unroll
                for (int v = 0; v < 8; v++) {
                    const float bx=a1[v*3], by=a1[v*3+1], bz=a1[v*3+2];
                    const u64t cx = dup2(ay*bz - az*by);
                    const u64t cy = dup2(az*bx - ax*bz);
                    const u64t cz = dup2(ax*by - ay*bx);
                    const ulonglong2* wp = (const ulonglong2*)(sm + O_W211 + (u*8+v)*8);
                    const ulonglong2 ta = wp[0], tb = wp[1];
                    const u64t wv[4] = {ta.x, ta.y, tb.x, tb.y};
                    #pragma unroll
                    for (int w2 = 0; w2 < 4; w2++) {
                        o1[w2*3+0] = f2fma(cx, wv[w2], o1[w2*3+0]);
                        o1[w2*3+1] = f2fma(cy, wv[w2], o1[w2*3+1]);
                        o1[w2*3+2] = f2fma(cz, wv[w2], o1[w2*3+2]);
                    }
                }
            }
            // unpack [w2][i] -> [w][i] and store
            float o1s[24];
            #pragma unroll
            for (int w2 = 0; w2 < 4; w2++) {
                #pragma unroll
                for (int i = 0; i < 3; i++) {
                    float2 t = up2(o1[w2*3+i]);
                    o1s[(2*w2+0)*3+i] = t.x;
                    o1s[(2*w2+1)*3+i] = t.y;
                }
            }
            float4* o4 = (float4*)(orow + 16);
            #pragma unroll
            for (int q = 0; q < 6; q++)
                o4[q] = make_float4(o1s[4*q], o1s[4*q+1], o1s[4*q+2], o1s[4*q+3]);
        }

        // ================= out2 (8x1e -> 24) =================
        {
            u64t o2[12];
            #pragma unroll
            for (int j = 0; j < 12; j++) o2[j] = 0ull;

            u64t M[32];
            // path (0,2,2)
            #pragma unroll
            for (int j = 0; j < 32; j++) M[j] = 0ull;
            #pragma unroll
            for (int u = 0; u < 16; u++) {
                const u64t hu2 = dup2(h0[u]);
                const ulonglong2* wp = (const ulonglong2*)(sm + O_W022 + u*64);
                #pragma unroll
                for (int j = 0; j < 16; j++) {
                    const ulonglong2 t = wp[j];
                    M[2*j+0] = f2fma(hu2, t.x, M[2*j+0]);
                    M[2*j+1] = f2fma(hu2, t.y, M[2*j+1]);
                }
            }
            #pragma unroll
            for (int v = 0; v < 8; v++) {
                const u64t b0 = dup2(a2[v*3]), b1 = dup2(a2[v*3+1]), b2 = dup2(a2[v*3+2]);
                #pragma unroll
                for (int w2 = 0; w2 < 4; w2++) {
                    const u64t m = M[v*4 + w2];
                    o2[w2*3+0] = f2fma(b0, m, o2[w2*3+0]);
                    o2[w2*3+1] = f2fma(b1, m, o2[w2*3+1]);
                    o2[w2*3+2] = f2fma(b2, m, o2[w2*3+2]);
                }
            }
            // path (2,0,2)
            #pragma unroll
            for (int j = 0; j < 32; j++) M[j] = 0ull;
            #pragma unroll
            for (int v = 0; v < 16; v++) {
                const u64t av2 = dup2(a0[v]);
                #pragma unroll
                for (int u = 0; u < 8; u++) {
                    const ulonglong2* wp = (const ulonglong2*)(sm + O_W202 + u*128 + v*8);
                    const ulonglong2 ta = wp[0], tb = wp[1];
                    M[u*4+0] = f2fma(av2, ta.x, M[u*4+0]);
                    M[u*4+1] = f2fma(av2, ta.y, M[u*4+1]);
                    M[u*4+2] = f2fma(av2, tb.x, M[u*4+2]);
                    M[u*4+3] = f2fma(av2, tb.y, M[u*4+3]);
                }
            }
            #pragma unroll
            for (int u = 0; u < 8; u++) {
                const u64t b0 = dup2(h2[u*3]), b1 = dup2(h2[u*3+1]), b2 = dup2(h2[u*3+2]);
                #pragma unroll
                for (int w2 = 0; w2 < 4; w2++) {
                    const u64t m = M[u*4 + w2];
                    o2[w2*3+0] = f2fma(b0, m, o2[w2*3+0]);
                    o2[w2*3+1] = f2fma(b1, m, o2[w2*3+1]);
                    o2[w2*3+2] = f2fma(b2, m, o2[w2*3+2]);
                }
            }
            // path (1,1,2): cross(h1[u], a1[v])
            #pragma unroll
            for (int u = 0; u < 8; u++) {
                const float ax=h1[u*3], ay=h1[u*3+1], az=h1[u*3+2];
                #pragma unroll
                for (int v = 0; v < 8; v++) {
                    const float bx=a1[v*3], by=a1[v*3+1], bz=a1[v*3+2];
                    const u64t cx = dup2(ay*bz - az*by);
                    const u64t cy = dup2(az*bx - ax*bz);
                    const u64t cz = dup2(ax*by - ay*bx);
                    const ulonglong2* wp = (const ulonglong2*)(sm + O_W112 + (u*8+v)*8);
                    const ulonglong2 ta = wp[0], tb = wp[1];
                    const u64t wv[4] = {ta.x, ta.y, tb.x, tb.y};
                    #pragma unroll
                    for (int w2 = 0; w2 < 4; w2++) {
                        o2[w2*3+0] = f2fma(cx, wv[w2], o2[w2*3+0]);
                        o2[w2*3+1] = f2fma(cy, wv[w2], o2[w2*3+1]);
                        o2[w2*3+2] = f2fma(cz, wv[w2], o2[w2*3+2]);
                    }
                }
            }
            // path (2,2,2): cross(h2[u], a2[v])
            #pragma unroll
            for (int u = 0; u < 8; u++) {
                const float ax=h2[u*3], ay=h2[u*3+1], az=h2[u*3+2];
                #pragma unroll
                for (int v = 0; v < 8; v++) {
                    const float bx=a2[v*3], by=a2[v*3+1], bz=a2[v*3+2];
                    const u64t cx = dup2(ay*bz - az*by);
                    const u64t cy = dup2(az*bx - ax*bz);
                    const u64t cz = dup2(ax*by - ay*bx);
                    const ulonglong2* wp = (const ulonglong2*)(sm + O_W222 + (u*8+v)*8);
                    const ulonglong2 ta = wp[0], tb = wp[1];
                    const u64t wv[4] = {ta.x, ta.y, tb.x, tb.y};
                    #pragma unroll
                    for (int w2 = 0; w2 < 4; w2++) {
                        o2[w2*3+0] = f2fma(cx, wv[w2], o2[w2*3+0]);
                        o2[w2*3+1] = f2fma(cy, wv[w2], o2[w2*3+1]);
                        o2[w2*3+2] = f2fma(cz, wv[w2], o2[w2*3+2]);
                    }
                }
            }
            float o2s[24];
            #pragma unroll
            for (int w2 = 0; w2 < 4; w2++) {
                #pragma unroll
                for (int i = 0; i < 3; i++) {
                    float2 t = up2(o2[w2*3+i]);
                    o2s[(2*w2+0)*3+i] = t.x;
                    o2s[(2*w2+1)*3+i] = t.y;
                }
            }
            float4* o4 = (float4*)(orow + 40);
            #pragma unroll
            for (int q = 0; q < 6; q++)
                o4[q] = make_float4(o2s[4*q], o2s[4*q+1], o2s[4*q+2], o2s[4*q+3]);
        }
    }
}

extern "C" void kernel_launch(void* const* d_in, const int* in_sizes, int n_in,
                              void* d_out, int out_size)
{
    const float* x    = (const float*)d_in[0];
    const float* l0h  = (const float*)d_in[1];
    const float* l1h  = (const float*)d_in[2];
    const float* l2h  = (const float*)d_in[3];
    const float* l0a  = (const float*)d_in[4];
    const float* l1a  = (const float*)d_in[5];
    const float* l2a  = (const float*)d_in[6];
    const float* w000 = (const float*)d_in[7];
    const float* w110 = (const float*)d_in[8];
    const float* w220 = (const float*)d_in[9];
    const float* w011 = (const float*)d_in[10];
    const float* w101 = (const float*)d_in[11];
    const float* w121 = (const float*)d_in[12];
    const float* w211 = (const float*)d_in[13];
    const float* w022 = (const float*)d_in[14];
    const float* w202 = (const float*)d_in[15];
    const float* w112 = (const float*)d_in[16];
    const float* w222 = (const float*)d_in[17];
    float* out = (float*)d_out;

    const int rows = in_sizes[0] / 64;
    const size_t smem_bytes = SMEM_FLOATS * sizeof(float);
    cudaFuncSetAttribute(e3nn_fctp_kernel,
                         cudaFuncAttributeMaxDynamicSharedMemorySize,
                         (int)smem_bytes);

    const int block = 256;
    const int grid = 1024;
    e3nn_fctp_kernel<<<grid, block, smem_bytes>>>(
        x, l0h, l1h, l2h, l0a, l1a, l2a,
        w000, w110, w220, w011, w101, w121, w211, w022, w202, w112, w222,
        out, rows);
}

// round 3
// speedup vs baseline: 1.5416x; 1.0196x over previous
#include <cuda_runtime.h>
#include <cstdint>

// ---------------- shared-memory weight layout (floats) ----------------
constexpr int O_L0H  = 0;      // 256  (16x16)
constexpr int O_L1H  = 256;    // 64   (8x8)
constexpr int O_L2H  = 320;    // 64
constexpr int O_L0A  = 384;    // 256
constexpr int O_L1A  = 640;    // 64
constexpr int O_L2A  = 704;    // 64
constexpr int O_W000 = 768;    // 4096 (16,16,16)
constexpr int O_W110 = 4864;   // 1024 (8,8,16)
constexpr int O_W220 = 5888;   // 1024
constexpr int O_W011 = 6912;   // 1024 (16,8,8)
constexpr int O_W101 = 7936;   // 1024 (8,16,8)
constexpr int O_W121 = 8960;   // 512  (8,8,8)
constexpr int O_W211 = 9472;   // 512
constexpr int O_W022 = 9984;   // 1024 (16,8,8)
constexpr int O_W202 = 11008;  // 1024 (8,16,8)
constexpr int O_W112 = 12032;  // 512
constexpr int O_W222 = 12544;  // 512
constexpr int SMEM_FLOATS = 13056;   // 52224 bytes

using u64t = unsigned long long;

__device__ __forceinline__ u64t pk2(float lo, float hi) {
    u64t r; asm("mov.b64 %0,{%1,%2};" : "=l"(r) : "f"(lo), "f"(hi)); return r;
}
__device__ __forceinline__ u64t dup2(float v) { return pk2(v, v); }
__device__ __forceinline__ float2 up2(u64t p) {
    float2 t; asm("mov.b64 {%0,%1},%2;" : "=f"(t.x), "=f"(t.y) : "l"(p)); return t;
}
__device__ __forceinline__ u64t f2fma(u64t a, u64t b, u64t c) {
    u64t d; asm("fma.rn.f32x2 %0,%1,%2,%3;" : "=l"(d) : "l"(a), "l"(b), "l"(c)); return d;
}
__device__ __forceinline__ u64t f2mul(u64t a, u64t b) {
    u64t d; asm("mul.rn.f32x2 %0,%1,%2;" : "=l"(d) : "l"(a), "l"(b)); return d;
}

__device__ __forceinline__ float sigm(float v) {
    return 1.0f / (1.0f + __expf(-v));
}

__global__ void __launch_bounds__(256, 2)
e3nn_fctp_kernel(const float* __restrict__ x,
                 const float* __restrict__ l0h, const float* __restrict__ l1h, const float* __restrict__ l2h,
                 const float* __restrict__ l0a, const float* __restrict__ l1a, const float* __restrict__ l2a,
                 const float* __restrict__ w000, const float* __restrict__ w110, const float* __restrict__ w220,
                 const float* __restrict__ w011, const float* __restrict__ w101, const float* __restrict__ w121,
                 const float* __restrict__ w211, const float* __restrict__ w022, const float* __restrict__ w202,
                 const float* __restrict__ w112, const float* __restrict__ w222,
                 float* __restrict__ out, int rows)
{
    extern __shared__ float sm[];
    const int tid = threadIdx.x;

    // path normalizations (folded into the smem weight copies)
    const float s0   = 0.051031036307982884f;   // sqrt(1/384)
    const float s1   = 0.088388347648318447f;   // sqrt(3/384)
    const float i3   = 0.57735026918962576f;    // 1/sqrt(3)
    const float i6   = 0.40824829046386302f;    // 1/sqrt(6)
    const float c110 = s0 * i3;
    const float c1_3 = s1 * i3;
    const float c1_6 = s1 * i6;
    const float lin16 = 0.25f;                  // 1/sqrt(16)
    const float lin8  = 0.35355339059327379f;   // 1/sqrt(8)

    // ---- preprocess weights into shared memory (scaled) ----
    sm[O_L0H + tid] = l0h[tid] * lin16;
    sm[O_L0A + tid] = l0a[tid] * lin16;
    if (tid < 64) {
        sm[O_L1H + tid] = l1h[tid] * lin8;
        sm[O_L2H + tid] = l2h[tid] * lin8;
        sm[O_L1A + tid] = l1a[tid] * lin8;
        sm[O_L2A + tid] = l2a[tid] * lin8;
    }
    #pragma unroll
    for (int q = 0; q < 16; q++) {
        int i = q * 256 + tid;
        sm[O_W000 + i] = w000[i] * s0;
    }
    #pragma unroll
    for (int q = 0; q < 4; q++) {
        int i = q * 256 + tid;
        sm[O_W110 + i] = w110[i] * c110;
        sm[O_W220 + i] = w220[i] * c110;
        sm[O_W011 + i] = w011[i] * c1_3;
        sm[O_W101 + i] = w101[i] * c1_3;
        sm[O_W022 + i] = w022[i] * c1_3;
        sm[O_W202 + i] = w202[i] * c1_3;
    }
    #pragma unroll
    for (int q = 0; q < 2; q++) {
        int i = q * 256 + tid;
        sm[O_W121 + i] = w121[i] * c1_6;
        sm[O_W211 + i] = w211[i] * c1_6;
        sm[O_W112 + i] = w112[i] * c1_6;
        sm[O_W222 + i] = w222[i] * c1_6;
    }
    __syncthreads();

    const int stride = gridDim.x * 256;
    #pragma unroll 1
    for (int row = blockIdx.x * 256 + tid; row < rows; row += stride) {
        const float* xr = x + (size_t)row * 64u;

        float h0[16], a0[16];
        float h1[24], a1[24], h2[24], a2[24];

        // ---- l=0 linear (packed over v pairs) ----
        {
            float xv0[16];
            #pragma unroll
            for (int q = 0; q < 4; q++) {
                float4 t = __ldg(((const float4*)xr) + q);
                xv0[4*q+0] = t.x; xv0[4*q+1] = t.y; xv0[4*q+2] = t.z; xv0[4*q+3] = t.w;
            }
            u64t h0p[8], a0p[8];
            #pragma unroll
            for (int q = 0; q < 8; q++) { h0p[q] = 0ull; a0p[q] = 0ull; }
            #pragma unroll
            for (int u = 0; u < 16; u++) {
                const u64t xu2 = dup2(xv0[u]);
                const ulonglong2* wh = (const ulonglong2*)(sm + O_L0H + u*16);
                const ulonglong2* wa = (const ulonglong2*)(sm + O_L0A + u*16);
                #pragma unroll
                for (int j = 0; j < 4; j++) {
                    const ulonglong2 th = wh[j];
                    h0p[2*j+0] = f2fma(xu2, th.x, h0p[2*j+0]);
                    h0p[2*j+1] = f2fma(xu2, th.y, h0p[2*j+1]);
                    const ulonglong2 ta = wa[j];
                    a0p[2*j+0] = f2fma(xu2, ta.x, a0p[2*j+0]);
                    a0p[2*j+1] = f2fma(xu2, ta.y, a0p[2*j+1]);
                }
            }
            #pragma unroll
            for (int q = 0; q < 8; q++) {
                float2 th = up2(h0p[q]); h0[2*q] = th.x; h0[2*q+1] = th.y;
                float2 ta = up2(a0p[q]); a0[2*q] = ta.x; a0[2*q+1] = ta.y;
            }
        }

        // ---- l=1 linears ----
        {
            float xv1[48];
            #pragma unroll
            for (int q = 0; q < 12; q++) {
                float4 t = __ldg(((const float4*)xr) + 4 + q);
                xv1[4*q+0] = t.x; xv1[4*q+1] = t.y; xv1[4*q+2] = t.z; xv1[4*q+3] = t.w;
            }
            #pragma unroll
            for (int j = 0; j < 24; j++) { h1[j]=0.f; a1[j]=0.f; h2[j]=0.f; a2[j]=0.f; }
            #pragma unroll
            for (int u = 0; u < 8; u++) {
                const float x10 = xv1[u*3+0], x11 = xv1[u*3+1], x12 = xv1[u*3+2];
                const float x20 = xv1[24+u*3+0], x21 = xv1[24+u*3+1], x22 = xv1[24+u*3+2];
                #pragma unroll
                for (int v = 0; v < 8; v++) {
                    const float wh1 = sm[O_L1H + u*8 + v];
                    const float wa1 = sm[O_L1A + u*8 + v];
                    const float wh2 = sm[O_L2H + u*8 + v];
                    const float wa2 = sm[O_L2A + u*8 + v];
                    h1[v*3+0] += x10*wh1; h1[v*3+1] += x11*wh1; h1[v*3+2] += x12*wh1;
                    a1[v*3+0] += x10*wa1; a1[v*3+1] += x11*wa1; a1[v*3+2] += x12*wa1;
                    h2[v*3+0] += x20*wh2; h2[v*3+1] += x21*wh2; h2[v*3+2] += x22*wh2;
                    a2[v*3+0] += x20*wa2; a2[v*3+1] += x21*wa2; a2[v*3+2] += x22*wa2;
                }
            }
        }

        // ---- NormActivation on a-branch ----
        #pragma unroll
        for (int u = 0; u < 16; u++) {
            const float v = a0[u];
            const float nn = fabsf(v);
            const float s = sigm(nn);
            a0[u] = (nn == 0.f) ? 0.f : v * s / nn;
        }
        #pragma unroll
        for (int u = 0; u < 8; u++) {
            {
                const float b0=a1[u*3], b1=a1[u*3+1], b2=a1[u*3+2];
                const float nrm = sqrtf(b0*b0 + b1*b1 + b2*b2);
                const float f = sigm(nrm) / ((nrm == 0.f) ? 1.f : nrm);
                a1[u*3] = b0*f; a1[u*3+1] = b1*f; a1[u*3+2] = b2*f;
            }
            {
                const float b0=a2[u*3], b1=a2[u*3+1], b2=a2[u*3+2];
                const float nrm = sqrtf(b0*b0 + b1*b1 + b2*b2);
                const float f = sigm(nrm) / ((nrm == 0.f) ? 1.f : nrm);
                a2[u*3] = b0*f; a2[u*3+1] = b1*f; a2[u*3+2] = b2*f;
            }
        }

        float* orow = out + (size_t)row * 64u;

        // ================= out0 (scalars, 16) — packed over w =================
        {
            u64t o0[8];
            #pragma unroll
            for (int q = 0; q < 8; q++) o0[q] = 0ull;

            // path (0,0,0): hoisted packed broadcasts of a0
            {
                u64t a0d[16];
                #pragma unroll
                for (int v = 0; v < 16; v++) a0d[v] = dup2(a0[v]);
                #pragma unroll
                for (int u = 0; u < 16; u++) {
                    const u64t hu2 = dup2(h0[u]);
                    #pragma unroll
                    for (int v = 0; v < 16; v++) {
                        const u64t p2 = f2mul(hu2, a0d[v]);
                        const ulonglong2* wp = (const ulonglong2*)(sm + O_W000 + (u*16 + v)*16);
                        #pragma unroll
                        for (int j = 0; j < 2; j++) {
                            const ulonglong2 t = wp[j];
                            o0[2*j+0] = f2fma(p2, t.x, o0[2*j+0]);
                            o0[2*j+1] = f2fma(p2, t.y, o0[2*j+1]);
                        }
                        #pragma unroll
                        for (int j = 2; j < 4; j++) {
                            const ulonglong2 t = wp[j];
                            o0[2*j+0] = f2fma(p2, t.x, o0[2*j+0]);
                            o0[2*j+1] = f2fma(p2, t.y, o0[2*j+1]);
                        }
                    }
                }
            }
            // path (1,1,0)
            #pragma unroll
            for (int u = 0; u < 8; u++) {
                const float hxx=h1[u*3], hyy=h1[u*3+1], hzz=h1[u*3+2];
                #pragma unroll
                for (int v = 0; v < 8; v++) {
                    const float d = hxx*a1[v*3] + hyy*a1[v*3+1] + hzz*a1[v*3+2];
                    const u64t d2 = dup2(d);
                    const ulonglong2* wp = (const ulonglong2*)(sm + O_W110 + (u*8 + v)*16);
                    #pragma unroll
                    for (int j = 0; j < 4; j++) {
                        const ulonglong2 t = wp[j];
                        o0[2*j+0] = f2fma(d2, t.x, o0[2*j+0]);
                        o0[2*j+1] = f2fma(d2, t.y, o0[2*j+1]);
                    }
                }
            }
            // path (2,2,0)
            #pragma unroll
            for (int u = 0; u < 8; u++) {
                const float hxx=h2[u*3], hyy=h2[u*3+1], hzz=h2[u*3+2];
                #pragma unroll
                for (int v = 0; v < 8; v++) {
                    const float d = hxx*a2[v*3] + hyy*a2[v*3+1] + hzz*a2[v*3+2];
                    const u64t d2 = dup2(d);
                    const ulonglong2* wp = (const ulonglong2*)(sm + O_W220 + (u*8 + v)*16);
                    #pragma unroll
                    for (int j = 0; j < 4; j++) {
                        const ulonglong2 t = wp[j];
                        o0[2*j+0] = f2fma(d2, t.x, o0[2*j+0]);
                        o0[2*j+1] = f2fma(d2, t.y, o0[2*j+1]);
                    }
                }
            }
            ulonglong2* o4 = (ulonglong2*)orow;
            #pragma unroll
            for (int j = 0; j < 4; j++) {
                ulonglong2 t; t.x = o0[2*j]; t.y = o0[2*j+1];
                o4[j] = t;
            }
        }

        // ================= out1 (8x1o -> 24) =================
        {
            u64t o1[12];   // o1[w2*3+i] = comp i for outputs (2*w2, 2*w2+1)
            #pragma unroll
            for (int j = 0; j < 12; j++) o1[j] = 0ull;

            // path (0,1,1): chunked over v (2 chunks of 4) to cap M regs
            #pragma unroll
            for (int vc = 0; vc < 2; vc++) {
                u64t Mc[16];   // [vl*4 + w2]
                #pragma unroll
                for (int j = 0; j < 16; j++) Mc[j] = 0ull;
                #pragma unroll
                for (int u = 0; u < 16; u++) {
                    const u64t hu2 = dup2(h0[u]);
                    const ulonglong2* wp = (const ulonglong2*)(sm + O_W011 + u*64 + vc*32);
                    #pragma unroll
                    for (int j = 0; j < 8; j++) {
                        const ulonglong2 t = wp[j];
                        Mc[2*j+0] = f2fma(hu2, t.x, Mc[2*j+0]);
                        Mc[2*j+1] = f2fma(hu2, t.y, Mc[2*j+1]);
                    }
                }
                #pragma unroll
                for (int vl = 0; vl < 4; vl++) {
                    const int v = vc*4 + vl;
                    const u64t b0 = dup2(a1[v*3]), b1 = dup2(a1[v*3+1]), b2 = dup2(a1[v*3+2]);
                    #pragma unroll
                    for (int w2 = 0; w2 < 4; w2++) {
                        const u64t m = Mc[vl*4 + w2];
                        o1[w2*3+0] = f2fma(b0, m, o1[w2*3+0]);
                        o1[w2*3+1] = f2fma(b1, m, o1[w2*3+1]);
                        o1[w2*3+2] = f2fma(b2, m, o1[w2*3+2]);
                    }
                }
            }
            // path (1,0,1): chunked over u (2 chunks of 4)
            #pragma unroll
            for (int uc = 0; uc < 2; uc++) {
                u64t Mc[16];   // [ul*4 + w2]
                #pragma unroll
                for (int j = 0; j < 16; j++) Mc[j] = 0ull;
                #pragma unroll
                for (int v = 0; v < 16; v++) {
                    const u64t av2 = dup2(a0[v]);
                    #pragma unroll
                    for (int ul = 0; ul < 4; ul++) {
                        const int u = uc*4 + ul;
                        const ulonglong2* wp = (const ulonglong2*)(sm + O_W101 + u*128 + v*8);
                        const ulonglong2 ta = wp[0], tb = wp[1];
                        Mc[ul*4+0] = f2fma(av2, ta.x, Mc[ul*4+0]);
                        Mc[ul*4+1] = f2fma(av2, ta.y, Mc[ul*4+1]);
                        Mc[ul*4+2] = f2fma(av2, tb.x, Mc[ul*4+2]);
                        Mc[ul*4+3] = f2fma(av2, tb.y, Mc[ul*4+3]);
                    }
                }
                #pragma unroll
                for (int ul = 0; ul < 4; ul++) {
                    const int u = uc*4 + ul;
                    const u64t b0 = dup2(h1[u*3]), b1 = dup2(h1[u*3+1]), b2 = dup2(h1[u*3+2]);
                    #pragma unroll
                    for (int w2 = 0; w2 < 4; w2++) {
                        const u64t m = Mc[ul*4 + w2];
                        o1[w2*3+0] = f2fma(b0, m, o1[w2*3+0]);
                        o1[w2*3+1] = f2fma(b1, m, o1[w2*3+1]);
                        o1[w2*3+2] = f2fma(b2, m, o1[w2*3+2]);
                    }
                }
            }
            // path (1,2,1): cross(h1[u], a2[v])
            #pragma unroll
            for (int u = 0; u < 8; u++) {
                const float ax=h1[u*3], ay=h1[u*3+1], az=h1[u*3+2];
                #pragma unroll
                for (int v = 0; v < 8; v++) {
                    const float bx=a2[v*3], by=a2[v*3+1], bz=a2[v*3+2];
                    const u64t cx = dup2(ay*bz - az*by);
                    const u64t cy = dup2(az*bx - ax*bz);
                    const u64t cz = dup2(ax*by - ay*bx);
                    const ulonglong2* wp = (const ulonglong2*)(sm + O_W121 + (u*8+v)*8);
                    const ulonglong2 ta = wp[0], tb = wp[1];
                    const u64t wv[4] = {ta.x, ta.y, tb.x, tb.y};
                    #pragma unroll
                    for (int w2 = 0; w2 < 4; w2++) {
                        o1[w2*3+0] = f2fma(cx, wv[w2], o1[w2*3+0]);
                        o1[w2*3+1] = f2fma(cy, wv[w2], o1[w2*3+1]);
                        o1[w2*3+2] = f2fma(cz, wv[w2], o1[w2*3+2]);
                    }
                }
            }
            // path (2,1,1): cross(h2[u], a1[v])
            #pragma unroll
            for (int u = 0; u < 8; u++) {
                const float ax=h2[u*3], ay=h2[u*3+1], az=h2[u*3+2];
                #pragma unroll
                for (int v = 0; v < 8; v++) {
                    const float bx=a1[v*3], by=a1[v*3+1], bz=a1[v*3+2];
                    const u64t cx = dup2(ay*bz - az*by);
                    const u64t cy = dup2(az*bx - ax*bz);
                    const u64t cz = dup2(ax*by - ay*bx);
                    const ulonglong2* wp = (const ulonglong2*)(sm + O_W211 + (u*8+v)*8);
                    const ulonglong2 ta = wp[0], tb = wp[1];
                    const u64t wv[4] = {ta.x, ta.y, tb.x, tb.y};
                    #pragma unroll
                    for (int w2 = 0; w2 < 4; w2++) {
                        o1[w2*3+0] = f2fma(cx, wv[w2], o1[w2*3+0]);
                        o1[w2*3+1] = f2fma(cy, wv[w2], o1[w2*3+1]);
                        o1[w2*3+2] = f2fma(cz, wv[w2], o1[w2*3+2]);
                    }
                }
            }
            // unpack [w2][i] -> [w][i] and store
            float o1s[24];
            #pragma unroll
            for (int w2 = 0; w2 < 4; w2++) {
                #pragma unroll
                for (int i = 0; i < 3; i++) {
                    float2 t = up2(o1[w2*3+i]);
                    o1s[(2*w2+0)*3+i] = t.x;
                    o1s[(2*w2+1)*3+i] = t.y;
                }
            }
            float4* o4 = (float4*)(orow + 16);
            #pragma unroll
            for (int q = 0; q < 6; q++)
                o4[q] = make_float4(o1s[4*q], o1s[4*q+1], o1s[4*q+2], o1s[4*q+3]);
        }

        // ================= out2 (8x1e -> 24) =================
        {
            u64t o2[12];
            #pragma unroll
            for (int j = 0; j < 12; j++) o2[j] = 0ull;

            // path (0,2,2): chunked over v
            #pragma unroll
            for (int vc = 0; vc < 2; vc++) {
                u64t Mc[16];
                #pragma unroll
                for (int j = 0; j < 16; j++) Mc[j] = 0ull;
                #pragma unroll
                for (int u = 0; u < 16; u++) {
                    const u64t hu2 = dup2(h0[u]);
                    const ulonglong2* wp = (const ulonglong2*)(sm + O_W022 + u*64 + vc*32);
                    #pragma unroll
                    for (int j = 0; j < 8; j++) {
                        const ulonglong2 t = wp[j];
                        Mc[2*j+0] = f2fma(hu2, t.x, Mc[2*j+0]);
                        Mc[2*j+1] = f2fma(hu2, t.y, Mc[2*j+1]);
                    }
                }
                #pragma unroll
                for (int vl = 0; vl < 4; vl++) {
                    const int v = vc*4 + vl;
                    const u64t b0 = dup2(a2[v*3]), b1 = dup2(a2[v*3+1]), b2 = dup2(a2[v*3+2]);
                    #pragma unroll
                    for (int w2 = 0; w2 < 4; w2++) {
                        const u64t m = Mc[vl*4 + w2];
                        o2[w2*3+0] = f2fma(b0, m, o2[w2*3+0]);
                        o2[w2*3+1] = f2fma(b1, m, o2[w2*3+1]);
                        o2[w2*3+2] = f2fma(b2, m, o2[w2*3+2]);
                    }
                }
            }
            // path (2,0,2): chunked over u
            #pragma unroll
            for (int uc = 0; uc < 2; uc++) {
                u64t Mc[16];
                #pragma unroll
                for (int j = 0; j < 16; j++) Mc[j] = 0ull;
                #pragma unroll
                for (int v = 0; v < 16; v++) {
                    const u64t av2 = dup2(a0[v]);
                    #pragma unroll
                    for (int ul = 0; ul < 4; ul++) {
                        const int u = uc*4 + ul;
                        const ulonglong2* wp = (const ulonglong2*)(sm + O_W202 + u*128 + v*8);
                        const ulonglong2 ta = wp[0], tb = wp[1];
                        Mc[ul*4+0] = f2fma(av2, ta.x, Mc[ul*4+0]);
                        Mc[ul*4+1] = f2fma(av2, ta.y, Mc[ul*4+1]);
                        Mc[ul*4+2] = f2fma(av2, tb.x, Mc[ul*4+2]);
                        Mc[ul*4+3] = f2fma(av2, tb.y, Mc[ul*4+3]);
                    }
                }
                #pragma unroll
                for (int ul = 0; ul < 4; ul++) {
                    const int u = uc*4 + ul;
                    const u64t b0 = dup2(h2[u*3]), b1 = dup2(h2[u*3+1]), b2 = dup2(h2[u*3+2]);
                    #pragma unroll
                    for (int w2 = 0; w2 < 4; w2++) {
                        const u64t m = Mc[ul*4 + w2];
                        o2[w2*3+0] = f2fma(b0, m, o2[w2*3+0]);
                        o2[w2*3+1] = f2fma(b1, m, o2[w2*3+1]);
                        o2[w2*3+2] = f2fma(b2, m, o2[w2*3+2]);
                    }
                }
            }
            // path (1,1,2): cross(h1[u], a1[v])
            #pragma unroll
            for (int u = 0; u < 8; u++) {
                const float ax=h1[u*3], ay=h1[u*3+1], az=h1[u*3+2];
                #pragma unroll
                for (int v = 0; v < 8; v++) {
                    const float bx=a1[v*3], by=a1[v*3+1], bz=a1[v*3+2];
                    const u64t cx = dup2(ay*bz - az*by);
                    const u64t cy = dup2(az*bx - ax*bz);
                    const u64t cz = dup2(ax*by - ay*bx);
                    const ulonglong2* wp = (const ulonglong2*)(sm + O_W112 + (u*8+v)*8);
                    const ulonglong2 ta = wp[0], tb = wp[1];
                    const u64t wv[4] = {ta.x, ta.y, tb.x, tb.y};
                    #pragma unroll
                    for (int w2 = 0; w2 < 4; w2++) {
                        o2[w2*3+0] = f2fma(cx, wv[w2], o2[w2*3+0]);
                        o2[w2*3+1] = f2fma(cy, wv[w2], o2[w2*3+1]);
                        o2[w2*3+2] = f2fma(cz, wv[w2], o2[w2*3+2]);
                    }
                }
            }
            // path (2,2,2): cross(h2[u], a2[v])
            #pragma unroll
            for (int u = 0; u < 8; u++) {
                const float ax=h2[u*3], ay=h2[u*3+1], az=h2[u*3+2];
                #pragma unroll
                for (int v = 0; v < 8; v++) {
                    const float bx=a2[v*3], by=a2[v*3+1], bz=a2[v*3+2];
                    const u64t cx = dup2(ay*bz - az*by);
                    const u64t cy = dup2(az*bx - ax*bz);
                    const u64t cz = dup2(ax*by - ay*bx);
                    const ulonglong2* wp = (const ulonglong2*)(sm + O_W222 + (u*8+v)*8);
                    const ulonglong2 ta = wp[0], tb = wp[1];
                    const u64t wv[4] = {ta.x, ta.y, tb.x, tb.y};
                    #pragma unroll
                    for (int w2 = 0; w2 < 4; w2++) {
                        o2[w2*3+0] = f2fma(cx, wv[w2], o2[w2*3+0]);
                        o2[w2*3+1] = f2fma(cy, wv[w2], o2[w2*3+1]);
                        o2[w2*3+2] = f2fma(cz, wv[w2], o2[w2*3+2]);
                    }
                }
            }
            float o2s[24];
            #pragma unroll
            for (int w2 = 0; w2 < 4; w2++) {
                #pragma unroll
                for (int i = 0; i < 3; i++) {
                    float2 t = up2(o2[w2*3+i]);
                    o2s[(2*w2+0)*3+i] = t.x;
                    o2s[(2*w2+1)*3+i] = t.y;
                }
            }
            float4* o4 = (float4*)(orow + 40);
            #pragma unroll
            for (int q = 0; q < 6; q++)
                o4[q] = make_float4(o2s[4*q], o2s[4*q+1], o2s[4*q+2], o2s[4*q+3]);
        }
    }
}

extern "C" void kernel_launch(void* const* d_in, const int* in_sizes, int n_in,
                              void* d_out, int out_size)
{
    const float* x    = (const float*)d_in[0];
    const float* l0h  = (const float*)d_in[1];
    const float* l1h  = (const float*)d_in[2];
    const float* l2h  = (const float*)d_in[3];
    const float* l0a  = (const float*)d_in[4];
    const float* l1a  = (const float*)d_in[5];
    const float* l2a  = (const float*)d_in[6];
    const float* w000 = (const float*)d_in[7];
    const float* w110 = (const float*)d_in[8];
    const float* w220 = (const float*)d_in[9];
    const float* w011 = (const float*)d_in[10];
    const float* w101 = (const float*)d_in[11];
    const float* w121 = (const float*)d_in[12];
    const float* w211 = (const float*)d_in[13];
    const float* w022 = (const float*)d_in[14];
    const float* w202 = (const float*)d_in[15];
    const float* w112 = (const float*)d_in[16];
    const float* w222 = (const float*)d_in[17];
    float* out = (float*)d_out;

    const int rows = in_sizes[0] / 64;
    const size_t smem_bytes = SMEM_FLOATS * sizeof(float);
    cudaFuncSetAttribute(e3nn_fctp_kernel,
                         cudaFuncAttributeMaxDynamicSharedMemorySize,
                         (int)smem_bytes);

    const int block = 256;
    const int grid = 1024;
    e3nn_fctp_kernel<<<grid, block, smem_bytes>>>(
        x, l0h, l1h, l2h, l0a, l1a, l2a,
        w000, w110, w220, w011, w101, w121, w211, w022, w202, w112, w222,
        out, rows);
}

// round 4
// speedup vs baseline: 1.6796x; 1.0895x over previous
#include <cuda_runtime.h>
#include <cstdint>

constexpr int NT = 192;

// ---------------- shared-memory layout (floats) ----------------
constexpr int O_L0H  = 0;      // 256  (16x16)
constexpr int O_L0A  = 256;    // 256
constexpr int O_IL1  = 512;    // 128: interleaved (h,a) weights for irrep-1 linear
constexpr int O_IL2  = 640;    // 128
constexpr int O_W000 = 768;    // 4096 (16,16,16)
constexpr int O_W110 = 4864;   // 1024 (8,8,16)
constexpr int O_W220 = 5888;   // 1024
constexpr int O_W011 = 6912;   // 1024 (16,8,8)
constexpr int O_W101 = 7936;   // 1024 (8,16,8)
constexpr int O_W121 = 8960;   // 512  (8,8,8)
constexpr int O_W211 = 9472;   // 512
constexpr int O_W022 = 9984;   // 1024 (16,8,8)
constexpr int O_W202 = 11008;  // 1024 (8,16,8)
constexpr int O_W112 = 12032;  // 512
constexpr int O_W222 = 12544;  // 512
// per-thread staging: [feat][tid], lane-indexed, conflict-free
constexpr int O_H1   = 13056;             // 24*NT
constexpr int O_A1   = O_H1 + 24*NT;      // 24*NT
constexpr int O_A2   = O_A1 + 24*NT;      // 24*NT
constexpr int SMEM_FLOATS = O_A2 + 24*NT; // 13056 + 13824 = 26880 (107,520 B)

using u64t = unsigned long long;

__device__ __forceinline__ u64t pk2(float lo, float hi) {
    u64t r; asm("mov.b64 %0,{%1,%2};" : "=l"(r) : "f"(lo), "f"(hi)); return r;
}
__device__ __forceinline__ u64t dup2(float v) { return pk2(v, v); }
__device__ __forceinline__ float2 up2(u64t p) {
    float2 t; asm("mov.b64 {%0,%1},%2;" : "=f"(t.x), "=f"(t.y) : "l"(p)); return t;
}
__device__ __forceinline__ u64t f2fma(u64t a, u64t b, u64t c) {
    u64t d; asm("fma.rn.f32x2 %0,%1,%2,%3;" : "=l"(d) : "l"(a), "l"(b), "l"(c)); return d;
}
__device__ __forceinline__ u64t f2mul(u64t a, u64t b) {
    u64t d; asm("mul.rn.f32x2 %0,%1,%2;" : "=l"(d) : "l"(a), "l"(b)); return d;
}
__device__ __forceinline__ float sigm(float v) {
    return 1.0f / (1.0f + __expf(-v));
}

__global__ void __launch_bounds__(NT, 2)
e3nn_fctp_kernel(const float* __restrict__ x,
                 const float* __restrict__ l0h, const float* __restrict__ l1h, const float* __restrict__ l2h,
                 const float* __restrict__ l0a, const float* __restrict__ l1a, const float* __restrict__ l2a,
                 const float* __restrict__ w000, const float* __restrict__ w110, const float* __restrict__ w220,
                 const float* __restrict__ w011, const float* __restrict__ w101, const float* __restrict__ w121,
                 const float* __restrict__ w211, const float* __restrict__ w022, const float* __restrict__ w202,
                 const float* __restrict__ w112, const float* __restrict__ w222,
                 float* __restrict__ out, int rows)
{
    extern __shared__ float sm[];
    const int tid = threadIdx.x;

    const float s0   = 0.051031036307982884f;   // sqrt(1/384)
    const float s1   = 0.088388347648318447f;   // sqrt(3/384)
    const float i3   = 0.57735026918962576f;    // 1/sqrt(3)
    const float i6   = 0.40824829046386302f;    // 1/sqrt(6)
    const float c110 = s0 * i3;
    const float c1_3 = s1 * i3;
    const float c1_6 = s1 * i6;
    const float lin16 = 0.25f;
    const float lin8  = 0.35355339059327379f;

    // ---- preprocess weights into shared memory (scaled) ----
    for (int i = tid; i < 256; i += NT) {
        sm[O_L0H + i] = l0h[i] * lin16;
        sm[O_L0A + i] = l0a[i] * lin16;
    }
    for (int i = tid; i < 64; i += NT) {
        sm[O_IL1 + 2*i+0] = l1h[i] * lin8;
        sm[O_IL1 + 2*i+1] = l1a[i] * lin8;
        sm[O_IL2 + 2*i+0] = l2h[i] * lin8;
        sm[O_IL2 + 2*i+1] = l2a[i] * lin8;
    }
    for (int i = tid; i < 4096; i += NT)
        sm[O_W000 + i] = w000[i] * s0;
    for (int i = tid; i < 1024; i += NT) {
        sm[O_W110 + i] = w110[i] * c110;
        sm[O_W220 + i] = w220[i] * c110;
        sm[O_W011 + i] = w011[i] * c1_3;
        sm[O_W101 + i] = w101[i] * c1_3;
        sm[O_W022 + i] = w022[i] * c1_3;
        sm[O_W202 + i] = w202[i] * c1_3;
    }
    for (int i = tid; i < 512; i += NT) {
        sm[O_W121 + i] = w121[i] * c1_6;
        sm[O_W211 + i] = w211[i] * c1_6;
        sm[O_W112 + i] = w112[i] * c1_6;
        sm[O_W222 + i] = w222[i] * c1_6;
    }
    __syncthreads();

    const float* sT = sm + tid;   // lane-indexed staging base
    const int stride = gridDim.x * NT;
    #pragma unroll 1
    for (int row = blockIdx.x * NT + tid; row < rows; row += stride) {
        const float* xr = x + (size_t)row * 64u;

        // ---- irrep-1 #1: h1 -> smem, a1(normact) -> smem ----
        {
            float xva[24];
            #pragma unroll
            for (int q = 0; q < 6; q++) {
                float4 t = __ldg((const float4*)(xr + 16) + q);
                xva[4*q+0]=t.x; xva[4*q+1]=t.y; xva[4*q+2]=t.z; xva[4*q+3]=t.w;
            }
            u64t ha[24];
            #pragma unroll
            for (int j = 0; j < 24; j++) ha[j] = 0ull;
            #pragma unroll
            for (int u = 0; u < 8; u++) {
                const u64t x0 = dup2(xva[u*3+0]), x1 = dup2(xva[u*3+1]), x2 = dup2(xva[u*3+2]);
                #pragma unroll
                for (int v = 0; v < 8; v++) {
                    const u64t w = *(const u64t*)(sm + O_IL1 + (u*8+v)*2);
                    ha[v*3+0] = f2fma(x0, w, ha[v*3+0]);
                    ha[v*3+1] = f2fma(x1, w, ha[v*3+1]);
                    ha[v*3+2] = f2fma(x2, w, ha[v*3+2]);
                }
            }
            #pragma unroll
            for (int v = 0; v < 8; v++) {
                float2 t0 = up2(ha[v*3+0]), t1 = up2(ha[v*3+1]), t2 = up2(ha[v*3+2]);
                const float b0 = t0.y, b1 = t1.y, b2 = t2.y;
                const float nrm = sqrtf(b0*b0 + b1*b1 + b2*b2);
                const float f = sigm(nrm) / ((nrm == 0.f) ? 1.f : nrm);
                sm[O_H1 + (v*3+0)*NT + tid] = t0.x;
                sm[O_H1 + (v*3+1)*NT + tid] = t1.x;
                sm[O_H1 + (v*3+2)*NT + tid] = t2.x;
                sm[O_A1 + (v*3+0)*NT + tid] = b0*f;
                sm[O_A1 + (v*3+1)*NT + tid] = b1*f;
                sm[O_A1 + (v*3+2)*NT + tid] = b2*f;
            }
        }

        // ---- irrep-1 #2: h2 stays in regs, a2(normact) -> smem ----
        float h2[24];
        {
            float xvb[24];
            #pragma unroll
            for (int q = 0; q < 6; q++) {
                float4 t = __ldg((const float4*)(xr + 40) + q);
                xvb[4*q+0]=t.x; xvb[4*q+1]=t.y; xvb[4*q+2]=t.z; xvb[4*q+3]=t.w;
            }
            u64t ha[24];
            #pragma unroll
            for (int j = 0; j < 24; j++) ha[j] = 0ull;
            #pragma unroll
            for (int u = 0; u < 8; u++) {
                const u64t x0 = dup2(xvb[u*3+0]), x1 = dup2(xvb[u*3+1]), x2 = dup2(xvb[u*3+2]);
                #pragma unroll
                for (int v = 0; v < 8; v++) {
                    const u64t w = *(const u64t*)(sm + O_IL2 + (u*8+v)*2);
                    ha[v*3+0] = f2fma(x0, w, ha[v*3+0]);
                    ha[v*3+1] = f2fma(x1, w, ha[v*3+1]);
                    ha[v*3+2] = f2fma(x2, w, ha[v*3+2]);
                }
            }
            #pragma unroll
            for (int v = 0; v < 8; v++) {
                float2 t0 = up2(ha[v*3+0]), t1 = up2(ha[v*3+1]), t2 = up2(ha[v*3+2]);
                const float b0 = t0.y, b1 = t1.y, b2 = t2.y;
                const float nrm = sqrtf(b0*b0 + b1*b1 + b2*b2);
                const float f = sigm(nrm) / ((nrm == 0.f) ? 1.f : nrm);
                h2[v*3+0] = t0.x; h2[v*3+1] = t1.x; h2[v*3+2] = t2.x;
                sm[O_A2 + (v*3+0)*NT + tid] = b0*f;
                sm[O_A2 + (v*3+1)*NT + tid] = b1*f;
                sm[O_A2 + (v*3+2)*NT + tid] = b2*f;
            }
        }

        // ---- l=0 linear: h0 scalars, a0 packed (post-normact) ----
        float h0[16];
        u64t a0d[16];
        {
            float xv0[16];
            #pragma unroll
            for (int q = 0; q < 4; q++) {
                float4 t = __ldg(((const float4*)xr) + q);
                xv0[4*q+0]=t.x; xv0[4*q+1]=t.y; xv0[4*q+2]=t.z; xv0[4*q+3]=t.w;
            }
            u64t h0p[8], a0p[8];
            #pragma unroll
            for (int q = 0; q < 8; q++) { h0p[q]=0ull; a0p[q]=0ull; }
            #pragma unroll
            for (int u = 0; u < 16; u++) {
                const u64t xu2 = dup2(xv0[u]);
                const ulonglong2* wh = (const ulonglong2*)(sm + O_L0H + u*16);
                const ulonglong2* wa = (const ulonglong2*)(sm + O_L0A + u*16);
                #pragma unroll
                for (int j = 0; j < 4; j++) {
                    const ulonglong2 th = wh[j];
                    h0p[2*j+0] = f2fma(xu2, th.x, h0p[2*j+0]);
                    h0p[2*j+1] = f2fma(xu2, th.y, h0p[2*j+1]);
                    const ulonglong2 ta = wa[j];
                    a0p[2*j+0] = f2fma(xu2, ta.x, a0p[2*j+0]);
                    a0p[2*j+1] = f2fma(xu2, ta.y, a0p[2*j+1]);
                }
            }
            #pragma unroll
            for (int q = 0; q < 8; q++) {
                float2 th = up2(h0p[q]); h0[2*q] = th.x; h0[2*q+1] = th.y;
                float2 ta = up2(a0p[q]);
                {
                    const float v = ta.x, nn = fabsf(v);
                    const float val = (nn == 0.f) ? 0.f : v * sigm(nn) / nn;
                    a0d[2*q] = dup2(val);
                }
                {
                    const float v = ta.y, nn = fabsf(v);
                    const float val = (nn == 0.f) ? 0.f : v * sigm(nn) / nn;
                    a0d[2*q+1] = dup2(val);
                }
            }
        }

        float* orow = out + (size_t)row * 64u;

        // ================= out0 (16 scalars, packed over w) =================
        {
            u64t o0[8];
            #pragma unroll
            for (int q = 0; q < 8; q++) o0[q] = 0ull;

            // path (0,0,0)
            #pragma unroll
            for (int u = 0; u < 16; u++) {
                const u64t hu2 = dup2(h0[u]);
                #pragma unroll
                for (int v = 0; v < 16; v++) {
                    const u64t p2 = f2mul(hu2, a0d[v]);
                    const ulonglong2* wp = (const ulonglong2*)(sm + O_W000 + (u*16 + v)*16);
                    const ulonglong2 ta = wp[0], tb = wp[1];
                    o0[0]=f2fma(p2,ta.x,o0[0]); o0[1]=f2fma(p2,ta.y,o0[1]);
                    o0[2]=f2fma(p2,tb.x,o0[2]); o0[3]=f2fma(p2,tb.y,o0[3]);
                    const ulonglong2 tc = wp[2], td = wp[3];
                    o0[4]=f2fma(p2,tc.x,o0[4]); o0[5]=f2fma(p2,tc.y,o0[5]);
                    o0[6]=f2fma(p2,td.x,o0[6]); o0[7]=f2fma(p2,td.y,o0[7]);
                }
            }
            // path (1,1,0): h1 streamed from smem, a1 hoisted
            {
                float a1r[24];
                #pragma unroll
                for (int f = 0; f < 24; f++) a1r[f] = sT[O_A1 + f*NT];
                #pragma unroll
                for (int u = 0; u < 8; u++) {
                    const float hx = sT[O_H1+(u*3+0)*NT], hy = sT[O_H1+(u*3+1)*NT], hz = sT[O_H1+(u*3+2)*NT];
                    #pragma unroll
                    for (int v = 0; v < 8; v++) {
                        const float d = hx*a1r[v*3] + hy*a1r[v*3+1] + hz*a1r[v*3+2];
                        const u64t d2 = dup2(d);
                        const ulonglong2* wp = (const ulonglong2*)(sm + O_W110 + (u*8 + v)*16);
                        const ulonglong2 ta = wp[0], tb = wp[1];
                        o0[0]=f2fma(d2,ta.x,o0[0]); o0[1]=f2fma(d2,ta.y,o0[1]);
                        o0[2]=f2fma(d2,tb.x,o0[2]); o0[3]=f2fma(d2,tb.y,o0[3]);
                        const ulonglong2 tc = wp[2], td = wp[3];
                        o0[4]=f2fma(d2,tc.x,o0[4]); o0[5]=f2fma(d2,tc.y,o0[5]);
                        o0[6]=f2fma(d2,td.x,o0[6]); o0[7]=f2fma(d2,td.y,o0[7]);
                    }
                }
            }
            // path (2,2,0): h2 in regs, a2 hoisted
            {
                float a2r[24];
                #pragma unroll
                for (int f = 0; f < 24; f++) a2r[f] = sT[O_A2 + f*NT];
                #pragma unroll
                for (int u = 0; u < 8; u++) {
                    const float hx = h2[u*3], hy = h2[u*3+1], hz = h2[u*3+2];
                    #pragma unroll
                    for (int v = 0; v < 8; v++) {
                        const float d = hx*a2r[v*3] + hy*a2r[v*3+1] + hz*a2r[v*3+2];
                        const u64t d2 = dup2(d);
                        const ulonglong2* wp = (const ulonglong2*)(sm + O_W220 + (u*8 + v)*16);
                        const ulonglong2 ta = wp[0], tb = wp[1];
                        o0[0]=f2fma(d2,ta.x,o0[0]); o0[1]=f2fma(d2,ta.y,o0[1]);
                        o0[2]=f2fma(d2,tb.x,o0[2]); o0[3]=f2fma(d2,tb.y,o0[3]);
                        const ulonglong2 tc = wp[2], td = wp[3];
                        o0[4]=f2fma(d2,tc.x,o0[4]); o0[5]=f2fma(d2,tc.y,o0[5]);
                        o0[6]=f2fma(d2,td.x,o0[6]); o0[7]=f2fma(d2,td.y,o0[7]);
                    }
                }
            }
            ulonglong2* o4 = (ulonglong2*)orow;
            #pragma unroll
            for (int j = 0; j < 4; j++) {
                ulonglong2 t; t.x = o0[2*j]; t.y = o0[2*j+1];
                o4[j] = t;
            }
        }

        // ================= out1 (8x1o -> 24) =================
        {
            u64t o1[12];
            #pragma unroll
            for (int j = 0; j < 12; j++) o1[j] = 0ull;

            // path (0,1,1): M[v,w] = sum_u h0[u]*W011[u,v,w], chunked over v
            #pragma unroll
            for (int vc = 0; vc < 2; vc++) {
                u64t Mc[16];
                #pragma unroll
                for (int j = 0; j < 16; j++) Mc[j] = 0ull;
                #pragma unroll
                for (int u = 0; u < 16; u++) {
                    const u64t hu2 = dup2(h0[u]);
                    const ulonglong2* wp = (const ulonglong2*)(sm + O_W011 + u*64 + vc*32);
                    #pragma unroll
                    for (int j = 0; j < 8; j++) {
                        const ulonglong2 t = wp[j];
                        Mc[2*j+0] = f2fma(hu2, t.x, Mc[2*j+0]);
                        Mc[2*j+1] = f2fma(hu2, t.y, Mc[2*j+1]);
                    }
                }
                #pragma unroll
                for (int vl = 0; vl < 4; vl++) {
                    const int v = vc*4 + vl;
                    const u64t b0 = dup2(sT[O_A1+(v*3+0)*NT]);
                    const u64t b1 = dup2(sT[O_A1+(v*3+1)*NT]);
                    const u64t b2 = dup2(sT[O_A1+(v*3+2)*NT]);
                    #pragma unroll
                    for (int w2 = 0; w2 < 4; w2++) {
                        const u64t m = Mc[vl*4 + w2];
                        o1[w2*3+0] = f2fma(b0, m, o1[w2*3+0]);
                        o1[w2*3+1] = f2fma(b1, m, o1[w2*3+1]);
                        o1[w2*3+2] = f2fma(b2, m, o1[w2*3+2]);
                    }
                }
            }
            // path (1,0,1): M[u,w] = sum_v a0[v]*W101[u,v,w], chunked over u
            #pragma unroll
            for (int uc = 0; uc < 2; uc++) {
                u64t Mc[16];
                #pragma unroll
                for (int j = 0; j < 16; j++) Mc[j] = 0ull;
                #pragma unroll
                for (int v = 0; v < 16; v++) {
                    const u64t av2 = a0d[v];
                    #pragma unroll
                    for (int ul = 0; ul < 4; ul++) {
                        const int u = uc*4 + ul;
                        const ulonglong2* wp = (const ulonglong2*)(sm + O_W101 + u*128 + v*8);
                        const ulonglong2 ta = wp[0], tb = wp[1];
                        Mc[ul*4+0] = f2fma(av2, ta.x, Mc[ul*4+0]);
                        Mc[ul*4+1] = f2fma(av2, ta.y, Mc[ul*4+1]);
                        Mc[ul*4+2] = f2fma(av2, tb.x, Mc[ul*4+2]);
                        Mc[ul*4+3] = f2fma(av2, tb.y, Mc[ul*4+3]);
                    }
                }
                #pragma unroll
                for (int ul = 0; ul < 4; ul++) {
                    const int u = uc*4 + ul;
                    const u64t b0 = dup2(sT[O_H1+(u*3+0)*NT]);
                    const u64t b1 = dup2(sT[O_H1+(u*3+1)*NT]);
                    const u64t b2 = dup2(sT[O_H1+(u*3+2)*NT]);
                    #pragma unroll
                    for (int w2 = 0; w2 < 4; w2++) {
                        const u64t m = Mc[ul*4 + w2];
                        o1[w2*3+0] = f2fma(b0, m, o1[w2*3+0]);
                        o1[w2*3+1] = f2fma(b1, m, o1[w2*3+1]);
                        o1[w2*3+2] = f2fma(b2, m, o1[w2*3+2]);
                    }
                }
            }
            // path (1,2,1): cross(h1[u] from smem, a2[v] hoisted)
            {
                float a2r[24];
                #pragma unroll
                for (int f = 0; f < 24; f++) a2r[f] = sT[O_A2 + f*NT];
                #pragma unroll
                for (int u = 0; u < 8; u++) {
                    const float ax = sT[O_H1+(u*3+0)*NT], ay = sT[O_H1+(u*3+1)*NT], az = sT[O_H1+(u*3+2)*NT];
                    #pragma unroll
                    for (int v = 0; v < 8; v++) {
                        const float bx=a2r[v*3], by=a2r[v*3+1], bz=a2r[v*3+2];
                        const u64t cx = dup2(ay*bz - az*by);
                        const u64t cy = dup2(az*bx - ax*bz);
                        const u64t cz = dup2(ax*by - ay*bx);
                        const ulonglong2* wp = (const ulonglong2*)(sm + O_W121 + (u*8+v)*8);
                        const ulonglong2 ta = wp[0], tb = wp[1];
                        const u64t wv[4] = {ta.x, ta.y, tb.x, tb.y};
                        #pragma unroll
                        for (int w2 = 0; w2 < 4; w2++) {
                            o1[w2*3+0] = f2fma(cx, wv[w2], o1[w2*3+0]);
                            o1[w2*3+1] = f2fma(cy, wv[w2], o1[w2*3+1]);
                            o1[w2*3+2] = f2fma(cz, wv[w2], o1[w2*3+2]);
                        }
                    }
                }
            }
            // path (2,1,1): cross(h2[u] regs, a1[v] hoisted)
            {
                float a1r[24];
                #pragma unroll
                for (int f = 0; f < 24; f++) a1r[f] = sT[O_A1 + f*NT];
                #pragma unroll
                for (int u = 0; u < 8; u++) {
                    const float ax = h2[u*3], ay = h2[u*3+1], az = h2[u*3+2];
                    #pragma unroll
                    for (int v = 0; v < 8; v++) {
                        const float bx=a1r[v*3], by=a1r[v*3+1], bz=a1r[v*3+2];
                        const u64t cx = dup2(ay*bz - az*by);
                        const u64t cy = dup2(az*bx - ax*bz);
                        const u64t cz = dup2(ax*by - ay*bx);
                        const ulonglong2* wp = (const ulonglong2*)(sm + O_W211 + (u*8+v)*8);
                        const ulonglong2 ta = wp[0], tb = wp[1];
                        const u64t wv[4] = {ta.x, ta.y, tb.x, tb.y};
                        #pragma unroll
                        for (int w2 = 0; w2 < 4; w2++) {
                            o1[w2*3+0] = f2fma(cx, wv[w2], o1[w2*3+0]);
                            o1[w2*3+1] = f2fma(cy, wv[w2], o1[w2*3+1]);
                            o1[w2*3+2] = f2fma(cz, wv[w2], o1[w2*3+2]);
                        }
                    }
                }
            }
            float o1s[24];
            #pragma unroll
            for (int w2 = 0; w2 < 4; w2++) {
                #pragma unroll
                for (int i = 0; i < 3; i++) {
                    float2 t = up2(o1[w2*3+i]);
                    o1s[(2*w2+0)*3+i] = t.x;
                    o1s[(2*w2+1)*3+i] = t.y;
                }
            }
            float4* o4 = (float4*)(orow + 16);
            #pragma unroll
            for (int q = 0; q < 6; q++)
                o4[q] = make_float4(o1s[4*q], o1s[4*q+1], o1s[4*q+2], o1s[4*q+3]);
        }

        // ================= out2 (8x1e -> 24) =================
        {
            u64t o2[12];
            #pragma unroll
            for (int j = 0; j < 12; j++) o2[j] = 0ull;

            // path (0,2,2): chunked over v, a2 streamed
            #pragma unroll
            for (int vc = 0; vc < 2; vc++) {
                u64t Mc[16];
                #pragma unroll
                for (int j = 0; j < 16; j++) Mc[j] = 0ull;
                #pragma unroll
                for (int u = 0; u < 16; u++) {
                    const u64t hu2 = dup2(h0[u]);
                    const ulonglong2* wp = (const ulonglong2*)(sm + O_W022 + u*64 + vc*32);
                    #pragma unroll
                    for (int j = 0; j < 8; j++) {
                        const ulonglong2 t = wp[j];
                        Mc[2*j+0] = f2fma(hu2, t.x, Mc[2*j+0]);
                        Mc[2*j+1] = f2fma(hu2, t.y, Mc[2*j+1]);
                    }
                }
                #pragma unroll
                for (int vl = 0; vl < 4; vl++) {
                    const int v = vc*4 + vl;
                    const u64t b0 = dup2(sT[O_A2+(v*3+0)*NT]);
                    const u64t b1 = dup2(sT[O_A2+(v*3+1)*NT]);
                    const u64t b2 = dup2(sT[O_A2+(v*3+2)*NT]);
                    #pragma unroll
                    for (int w2 = 0; w2 < 4; w2++) {
                        const u64t m = Mc[vl*4 + w2];
                        o2[w2*3+0] = f2fma(b0, m, o2[w2*3+0]);
                        o2[w2*3+1] = f2fma(b1, m, o2[w2*3+1]);
                        o2[w2*3+2] = f2fma(b2, m, o2[w2*3+2]);
                    }
                }
            }
            // path (2,0,2): chunked over u, h2 regs
            #pragma unroll
            for (int uc = 0; uc < 2; uc++) {
                u64t Mc[16];
                #pragma unroll
                for (int j = 0; j < 16; j++) Mc[j] = 0ull;
                #pragma unroll
                for (int v = 0; v < 16; v++) {
                    const u64t av2 = a0d[v];
                    #pragma unroll
                    for (int ul = 0; ul < 4; ul++) {
                        const int u = uc*4 + ul;
                        const ulonglong2* wp = (const ulonglong2*)(sm + O_W202 + u*128 + v*8);
                        const ulonglong2 ta = wp[0], tb = wp[1];
                        Mc[ul*4+0] = f2fma(av2, ta.x, Mc[ul*4+0]);
                        Mc[ul*4+1] = f2fma(av2, ta.y, Mc[ul*4+1]);
                        Mc[ul*4+2] = f2fma(av2, tb.x, Mc[ul*4+2]);
                        Mc[ul*4+3] = f2fma(av2, tb.y, Mc[ul*4+3]);
                    }
                }
                #pragma unroll
                for (int ul = 0; ul < 4; ul++) {
                    const int u = uc*4 + ul;
                    const u64t b0 = dup2(h2[u*3+0]);
                    const u64t b1 = dup2(h2[u*3+1]);
                    const u64t b2 = dup2(h2[u*3+2]);
                    #pragma unroll
                    for (int w2 = 0; w2 < 4; w2++) {
                        const u64t m = Mc[ul*4 + w2];
                        o2[w2*3+0] = f2fma(b0, m, o2[w2*3+0]);
                        o2[w2*3+1] = f2fma(b1, m, o2[w2*3+1]);
                        o2[w2*3+2] = f2fma(b2, m, o2[w2*3+2]);
                    }
                }
            }
            // path (1,1,2): cross(h1[u] smem, a1[v] hoisted)
            {
                float a1r[24];
                #pragma unroll
                for (int f = 0; f < 24; f++) a1r[f] = sT[O_A1 + f*NT];
                #pragma unroll
                for (int u = 0; u < 8; u++) {
                    const float ax = sT[O_H1+(u*3+0)*NT], ay = sT[O_H1+(u*3+1)*NT], az = sT[O_H1+(u*3+2)*NT];
                    #pragma unroll
                    for (int v = 0; v < 8; v++) {
                        const float bx=a1r[v*3], by=a1r[v*3+1], bz=a1r[v*3+2];
                        const u64t cx = dup2(ay*bz - az*by);
                        const u64t cy = dup2(az*bx - ax*bz);
                        const u64t cz = dup2(ax*by - ay*bx);
                        const ulonglong2* wp = (const ulonglong2*)(sm + O_W112 + (u*8+v)*8);
                        const ulonglong2 ta = wp[0], tb = wp[1];
                        const u64t wv[4] = {ta.x, ta.y, tb.x, tb.y};
                        #pragma unroll
                        for (int w2 = 0; w2 < 4; w2++) {
                            o2[w2*3+0] = f2fma(cx, wv[w2], o2[w2*3+0]);
                            o2[w2*3+1] = f2fma(cy, wv[w2], o2[w2*3+1]);
                            o2[w2*3+2] = f2fma(cz, wv[w2], o2[w2*3+2]);
                        }
                    }
                }
            }
            // path (2,2,2): cross(h2[u] regs, a2[v] hoisted)
            {
                float a2r[24];
                #pragma unroll
                for (int f = 0; f < 24; f++) a2r[f] = sT[O_A2 + f*NT];
                #pragma unroll
                for (int u = 0; u < 8; u++) {
                    const float ax = h2[u*3], ay = h2[u*3+1], az = h2[u*3+2];
                    #pragma unroll
                    for (int v = 0; v < 8; v++) {
                        const float bx=a2r[v*3], by=a2r[v*3+1], bz=a2r[v*3+2];
                        const u64t cx = dup2(ay*bz - az*by);
                        const u64t cy = dup2(az*bx - ax*bz);
                        const u64t cz = dup2(ax*by - ay*bx);
                        const ulonglong2* wp = (const ulonglong2*)(sm + O_W222 + (u*8+v)*8);
                        const ulonglong2 ta = wp[0], tb = wp[1];
                        const u64t wv[4] = {ta.x, ta.y, tb.x, tb.y};
                        #pragma unroll
                        for (int w2 = 0; w2 < 4; w2++) {
                            o2[w2*3+0] = f2fma(cx, wv[w2], o2[w2*3+0]);
                            o2[w2*3+1] = f2fma(cy, wv[w2], o2[w2*3+1]);
                            o2[w2*3+2] = f2fma(cz, wv[w2], o2[w2*3+2]);
                        }
                    }
                }
            }
            float o2s[24];
            #pragma unroll
            for (int w2 = 0; w2 < 4; w2++) {
                #pragma unroll
                for (int i = 0; i < 3; i++) {
                    float2 t = up2(o2[w2*3+i]);
                    o2s[(2*w2+0)*3+i] = t.x;
                    o2s[(2*w2+1)*3+i] = t.y;
                }
            }
            float4* o4 = (float4*)(orow + 40);
            #pragma unroll
            for (int q = 0; q < 6; q++)
                o4[q] = make_float4(o2s[4*q], o2s[4*q+1], o2s[4*q+2], o2s[4*q+3]);
        }
    }
}

extern "C" void kernel_launch(void* const* d_in, const int* in_sizes, int n_in,
                              void* d_out, int out_size)
{
    const float* x    = (const float*)d_in[0];
    const float* l0h  = (const float*)d_in[1];
    const float* l1h  = (const float*)d_in[2];
    const float* l2h  = (const float*)d_in[3];
    const float* l0a  = (const float*)d_in[4];
    const float* l1a  = (const float*)d_in[5];
    const float* l2a  = (const float*)d_in[6];
    const float* w000 = (const float*)d_in[7];
    const float* w110 = (const float*)d_in[8];
    const float* w220 = (const float*)d_in[9];
    const float* w011 = (const float*)d_in[10];
    const float* w101 = (const float*)d_in[11];
    const float* w121 = (const float*)d_in[12];
    const float* w211 = (const float*)d_in[13];
    const float* w022 = (const float*)d_in[14];
    const float* w202 = (const float*)d_in[15];
    const float* w112 = (const float*)d_in[16];
    const float* w222 = (const float*)d_in[17];
    float* out = (float*)d_out;

    const int rows = in_sizes[0] / 64;
    const size_t smem_bytes = SMEM_FLOATS * sizeof(float);
    cudaFuncSetAttribute(e3nn_fctp_kernel,
                         cudaFuncAttributeMaxDynamicSharedMemorySize,
                         (int)smem_bytes);

    // 2 rows per thread: amortize per-CTA weight preprocessing
    const int grid = (rows + 2*NT - 1) / (2*NT);
    e3nn_fctp_kernel<<<grid, NT, smem_bytes>>>(
        x, l0h, l1h, l2h, l0a, l1a, l2a,
        w000, w110, w220, w011, w101, w121, w211, w022, w202, w112, w222,
        out, rows);
}